// round 2
// baseline (speedup 1.0000x reference)
#include <cuda_runtime.h>
#include <math.h>

// Problem dims (fixed by the reference)
#define BB   2
#define SEQ  2048
#define DIM  768
#define NH   12
#define DHD  64
#define FFD  3072
#define PDIM 64
#define NROW (BB*SEQ)      // 4096

// ---------------- scratch (device globals; no cudaMalloc allowed) ----------
__device__ __align__(16) float g_xn[NROW*DIM];
__device__ __align__(16) float g_qk[NROW*2*DIM];
__device__ __align__(16) float g_phase[NROW*PDIM];
__device__ __align__(16) float g_scores[(size_t)BB*NH*SEQ*SEQ];   // exp(s/8)
__device__              float g_ssum[BB*NH*SEQ];                  // per-head row sums
__device__ __align__(16) float g_pc[(size_t)BB*SEQ*SEQ];          // exp(a*(pc+1)/2)
__device__ __align__(16) float g_blend[(size_t)BB*SEQ*SEQ];
__device__              float g_rowsum[BB*SEQ];
__device__ __align__(16) float g_xmid[NROW*DIM];
__device__ __align__(16) float g_x2[NROW*DIM];
__device__ __align__(16) float g_hbuf[NROW*FFD];

// ---------------- f32x2 packed-FMA helpers (Blackwell) ----------------------
__device__ __forceinline__ void ffma2(unsigned long long& acc,
                                      unsigned long long a, unsigned long long b) {
    asm("fma.rn.f32x2 %0, %1, %2, %0;" : "+l"(acc) : "l"(a), "l"(b));
}
__device__ __forceinline__ unsigned long long bcast2(float s) {
    unsigned long long d;
    asm("mov.b64 %0, {%1, %1};" : "=l"(d) : "f"(s));
    return d;
}
__device__ __forceinline__ void unpack2(unsigned long long v, float& lo, float& hi) {
    asm("mov.b64 {%0, %1}, %2;" : "=f"(lo), "=f"(hi) : "l"(v));
}

// ---------------- misc helpers ----------------------------------------------
__device__ __forceinline__ float warpReduceSum(float v) {
#pragma unroll
    for (int o = 16; o > 0; o >>= 1) v += __shfl_xor_sync(0xffffffffu, v, o);
    return v;
}
__device__ __forceinline__ float blockReduceSum256(float v, float* sm) {
    v = warpReduceSum(v);
    if ((threadIdx.x & 31) == 0) sm[threadIdx.x >> 5] = v;
    __syncthreads();
    if (threadIdx.x < 32) {
        float t = (threadIdx.x < 8) ? sm[threadIdx.x] : 0.0f;
        t = warpReduceSum(t);
        if (threadIdx.x == 0) sm[0] = t;
    }
    __syncthreads();
    float r = sm[0];
    __syncthreads();
    return r;
}

// Fast exp on the FMA pipe (no MUFU). Max rel err ~3e-6.
__device__ __forceinline__ float fast_exp(float x) {
    x = fmaxf(x, -87.0f);
    float y  = x * 1.4426950408889634f;
    float z  = y + 12582912.0f;                 // 1.5 * 2^23
    float nf = z - 12582912.0f;
    float f  = y - nf;
    float p  = 1.3333558146e-3f;
    p = fmaf(p, f, 9.6181291076e-3f);
    p = fmaf(p, f, 5.5504108665e-2f);
    p = fmaf(p, f, 2.4022650696e-1f);
    p = fmaf(p, f, 6.9314718056e-1f);
    p = fmaf(p, f, 1.0f);
    unsigned sb = ((unsigned)__float_as_int(z) + (unsigned)(127 - 0x4B400000)) << 23;
    return p * __int_as_float(sb);
}

// ---------------- LayerNorm ------------------------------------------------
__global__ void __launch_bounds__(256) ln_kernel(
    const float* __restrict__ x, const float* __restrict__ w,
    const float* __restrict__ b, float* __restrict__ o)
{
    __shared__ float sm[8];
    const float* xr = x + (size_t)blockIdx.x * DIM;
    int t = threadIdx.x;
    float v0 = xr[t], v1 = xr[t + 256], v2 = xr[t + 512];
    float mean = blockReduceSum256(v0 + v1 + v2, sm) * (1.0f / DIM);
    float d0 = v0 - mean, d1 = v1 - mean, d2 = v2 - mean;
    float var = blockReduceSum256(d0*d0 + d1*d1 + d2*d2, sm) * (1.0f / DIM);
    float r = rsqrtf(var + 1e-5f);
    float* orow = o + (size_t)blockIdx.x * DIM;
    orow[t      ] = d0 * r * w[t      ] + b[t      ];
    orow[t + 256] = d1 * r * w[t + 256] + b[t + 256];
    orow[t + 512] = d2 * r * w[t + 512] + b[t + 512];
}

__global__ void __launch_bounds__(256) zero_kernel(float* __restrict__ p, int n) {
    int i = blockIdx.x * 256 + threadIdx.x;
    if (i < n) p[i] = 0.0f;
}

// ============================================================================
// 128x128x16 FFMA2 SGEMM. 256 threads, TM=8 (paired along M), TN=8.
// TRB=true : B row-major [N,K] -> C = A@B^T ; TRB=false: B [K,N] -> C = A@B.
// EPI: 0=scale, 1=+bias, 3=bias+exact GELU, 4=bias+residual,
//      5=row-divide(rowsum)+residual, 6=exp(scale*v)+atomic rowsum,
//      7=exp(a2*v + a2) with a2 = 0.5*alpha   (phase coherence)
// ============================================================================
template<bool TRB, int EPI>
__global__ void __launch_bounds__(256, 1) gemm128(
    const float* __restrict__ A, const float* __restrict__ Bm,
    float* __restrict__ C,
    int M, int N, int K, int lda, int ldb, int ldc,
    int zdiv,
    long as1, long as2, long bs1, long bs2, long cs1, long cs2,
    float scale,
    const float* __restrict__ bias,
    const float* __restrict__ res, long ress1,
    const float* __restrict__ rsum, long rsums1,
    const float* __restrict__ alphap,
    float* __restrict__ ssum)
{
    const int BM = 128, BN = 128, BK = 16;
    int z = blockIdx.z;
    int z1 = z / zdiv, z2 = z - z1 * zdiv;
    A  += z1 * as1 + z2 * as2;
    Bm += z1 * bs1 + z2 * bs2;
    C  += z1 * cs1 + z2 * cs2;
    if (EPI == 4 || EPI == 5) res  += z1 * ress1;
    if (EPI == 5)             rsum += z1 * rsums1;
    if (EPI == 6)             ssum += (size_t)z * M;

    __shared__ float As[BK][BM + 4];
    __shared__ float Bs[BK][BN + 4];

    int tid = threadIdx.x;
    int tx = tid & 15, ty = tid >> 4;
    int bm = blockIdx.x * BM, bn = blockIdx.y * BN;

    unsigned long long acc[4][8];   // [m-pair][n], each packs (m_even, m_odd)
#pragma unroll
    for (int i = 0; i < 4; i++)
#pragma unroll
        for (int j = 0; j < 8; j++) acc[i][j] = 0ull;

    const float* Ab = A + (size_t)bm * lda;

    int ra = tid >> 2, ca = (tid & 3) << 2;        // A/B(TRB) staging coords
    int rb2 = tid >> 5, cb2 = (tid & 31) << 2;     // B(!TRB) staging coords

    float4 sA0, sA1, sB0, sB1;
    // ---- stage tile k0=0 into registers ----
    {
        sA0 = *(const float4*)(Ab + (size_t)ra * lda + ca);
        sA1 = *(const float4*)(Ab + (size_t)(ra + 64) * lda + ca);
        if (TRB) {
            sB0 = *(const float4*)(Bm + (size_t)(bn + ra) * ldb + ca);
            sB1 = *(const float4*)(Bm + (size_t)(bn + ra + 64) * ldb + ca);
        } else {
            sB0 = *(const float4*)(Bm + (size_t)rb2 * ldb + (bn + cb2));
            sB1 = *(const float4*)(Bm + (size_t)(rb2 + 8) * ldb + (bn + cb2));
        }
    }

    for (int k0 = 0; k0 < K; k0 += BK) {
        // commit staged tile to smem
        As[ca + 0][ra] = sA0.x; As[ca + 1][ra] = sA0.y;
        As[ca + 2][ra] = sA0.z; As[ca + 3][ra] = sA0.w;
        As[ca + 0][ra + 64] = sA1.x; As[ca + 1][ra + 64] = sA1.y;
        As[ca + 2][ra + 64] = sA1.z; As[ca + 3][ra + 64] = sA1.w;
        if (TRB) {
            Bs[ca + 0][ra] = sB0.x; Bs[ca + 1][ra] = sB0.y;
            Bs[ca + 2][ra] = sB0.z; Bs[ca + 3][ra] = sB0.w;
            Bs[ca + 0][ra + 64] = sB1.x; Bs[ca + 1][ra + 64] = sB1.y;
            Bs[ca + 2][ra + 64] = sB1.z; Bs[ca + 3][ra + 64] = sB1.w;
        } else {
            *(float4*)&Bs[rb2][cb2]     = sB0;
            *(float4*)&Bs[rb2 + 8][cb2] = sB1;
        }
        __syncthreads();

        // stage NEXT tile while computing this one
        int kn = k0 + BK;
        if (kn < K) {
            sA0 = *(const float4*)(Ab + (size_t)ra * lda + (kn + ca));
            sA1 = *(const float4*)(Ab + (size_t)(ra + 64) * lda + (kn + ca));
            if (TRB) {
                sB0 = *(const float4*)(Bm + (size_t)(bn + ra) * ldb + (kn + ca));
                sB1 = *(const float4*)(Bm + (size_t)(bn + ra + 64) * ldb + (kn + ca));
            } else {
                sB0 = *(const float4*)(Bm + (size_t)(kn + rb2) * ldb + (bn + cb2));
                sB1 = *(const float4*)(Bm + (size_t)(kn + rb2 + 8) * ldb + (bn + cb2));
            }
        }

#pragma unroll
        for (int kk = 0; kk < BK; kk++) {
            // A pairs come free from 128-bit LDS (consecutive M in memory)
            ulonglong2 aA = *(const ulonglong2*)&As[kk][ty * 8];
            ulonglong2 aB = *(const ulonglong2*)&As[kk][ty * 8 + 4];
            unsigned long long a2[4] = {aA.x, aA.y, aB.x, aB.y};
            float bf[8];
            *(float4*)&bf[0] = *(const float4*)&Bs[kk][tx * 8];
            *(float4*)&bf[4] = *(const float4*)&Bs[kk][tx * 8 + 4];
            unsigned long long bd[8];
#pragma unroll
            for (int j = 0; j < 8; j++) bd[j] = bcast2(bf[j]);
#pragma unroll
            for (int i = 0; i < 4; i++)
#pragma unroll
                for (int j = 0; j < 8; j++)
                    ffma2(acc[i][j], a2[i], bd[j]);
        }
        __syncthreads();
    }

    // ---------------- epilogue ----------------
    float a2v = 0.0f;
    if (EPI == 7) a2v = 0.5f * (*alphap);
    int n0 = bn + tx * 8;
    int lane = tid & 31;

#pragma unroll
    for (int ip = 0; ip < 4; ip++) {
        float vlo[8], vhi[8];
#pragma unroll
        for (int j = 0; j < 8; j++) unpack2(acc[ip][j], vlo[j], vhi[j]);
#pragma unroll
        for (int half = 0; half < 2; half++) {
            float* vv = half ? vhi : vlo;
            int m = bm + ty * 8 + ip * 2 + half;
            float rinv = 0.0f;
            if (EPI == 5) rinv = 1.0f / rsum[m];
#pragma unroll
            for (int j = 0; j < 8; j++) {
                float v = vv[j];
                int n = n0 + j;
                if (EPI == 0) v *= scale;
                if (EPI == 1) v += bias[n];
                if (EPI == 3) { v += bias[n]; v = 0.5f * v * (1.0f + erff(v * 0.70710678118654752f)); }
                if (EPI == 4) { v = v + bias[n] + res[(size_t)m * ldc + n]; }
                if (EPI == 5) { v = v * rinv + res[(size_t)m * ldc + n]; }
                if (EPI == 6) { v = fast_exp(v * scale); }
                if (EPI == 7) { v = fast_exp(fmaf(v, a2v, a2v)); }
                vv[j] = v;
            }
            if (EPI == 6) {
                float rs = 0.0f;
#pragma unroll
                for (int j = 0; j < 8; j++) rs += vv[j];
#pragma unroll
                for (int o = 8; o > 0; o >>= 1) rs += __shfl_xor_sync(0xffffffffu, rs, o);
                if ((lane & 15) == 0) atomicAdd(&ssum[m], rs);
            }
            float4 o0; o0.x = vv[0]; o0.y = vv[1]; o0.z = vv[2]; o0.w = vv[3];
            float4 o1; o1.x = vv[4]; o1.y = vv[5]; o1.z = vv[6]; o1.w = vv[7];
            *(float4*)(C + (size_t)m * ldc + n0)     = o0;
            *(float4*)(C + (size_t)m * ldc + n0 + 4) = o1;
        }
    }
}

// ---------------- small GEMM for phase (N=64): C = tanh(A @ B^T) ------------
__global__ void __launch_bounds__(256) phase_gemm(
    const float* __restrict__ A, const float* __restrict__ Bm,
    float* __restrict__ C)
{
    const int BM = 128, BN = 64, BK = 16, TM = 8, TN = 4;
    __shared__ float As[BK][BM + 4];
    __shared__ float Bs[BK][BN + 4];
    int tid = threadIdx.x;
    int tx = tid & 15, ty = tid >> 4;
    int bm = blockIdx.x * BM;
    float acc[TM][TN];
#pragma unroll
    for (int i = 0; i < TM; i++)
#pragma unroll
        for (int j = 0; j < TN; j++) acc[i][j] = 0.0f;
    const float* Ab = A + (size_t)bm * DIM;
    for (int k0 = 0; k0 < DIM; k0 += BK) {
#pragma unroll
        for (int i = 0; i < 2; i++) {
            int id = tid + i * 256;
            int r = id >> 2, c = (id & 3) << 2;
            const float4 v = *(const float4*)(Ab + (size_t)r * DIM + (k0 + c));
            As[c + 0][r] = v.x; As[c + 1][r] = v.y;
            As[c + 2][r] = v.z; As[c + 3][r] = v.w;
        }
        {
            int r = tid >> 2, c = (tid & 3) << 2;
            const float4 v = *(const float4*)(Bm + (size_t)r * DIM + (k0 + c));
            Bs[c + 0][r] = v.x; Bs[c + 1][r] = v.y;
            Bs[c + 2][r] = v.z; Bs[c + 3][r] = v.w;
        }
        __syncthreads();
#pragma unroll
        for (int kk = 0; kk < BK; kk++) {
            float af[TM], bf[TN];
            *(float4*)&af[0] = *(const float4*)&As[kk][ty * TM];
            *(float4*)&af[4] = *(const float4*)&As[kk][ty * TM + 4];
            *(float4*)&bf[0] = *(const float4*)&Bs[kk][tx * TN];
#pragma unroll
            for (int i = 0; i < TM; i++)
#pragma unroll
                for (int j = 0; j < TN; j++)
                    acc[i][j] = fmaf(af[i], bf[j], acc[i][j]);
        }
        __syncthreads();
    }
#pragma unroll
    for (int i = 0; i < TM; i++) {
        int m = bm + ty * TM + i;
        int n0 = tx * TN;
        float4 o;
        o.x = tanhf(acc[i][0]); o.y = tanhf(acc[i][1]);
        o.z = tanhf(acc[i][2]); o.w = tanhf(acc[i][3]);
        *(float4*)(C + (size_t)m * PDIM + n0) = o;
    }
}

// --------- blend: u = (mean_h softmax_h + 1e-6) * pcexp; rowsum -------------
__global__ void __launch_bounds__(256) blend_kernel(
    const float* __restrict__ scoresE, const float* __restrict__ ssum,
    const float* __restrict__ pcexp, float* __restrict__ blend,
    float* __restrict__ rowsum)
{
    __shared__ float sm[8];
    __shared__ float sinvl[NH];
    int b = blockIdx.x / SEQ;
    int i = blockIdx.x - b * SEQ;
    if (threadIdx.x < NH)
        sinvl[threadIdx.x] = 1.0f / (ssum[(b * NH + threadIdx.x) * SEQ + i] * (float)NH);
    __syncthreads();

    const float* ebase = scoresE + ((size_t)(b * NH) * SEQ + (size_t)i) * SEQ;
    const float* prow  = pcexp + ((size_t)b * SEQ + i) * SEQ;
    float*       brow  = blend + ((size_t)b * SEQ + i) * SEQ;

    float lsum = 0.0f;
    for (int j = threadIdx.x; j < SEQ; j += 256) {
        float w = 1e-6f;
#pragma unroll
        for (int h = 0; h < NH; h++)
            w = fmaf(ebase[(size_t)h * SEQ * SEQ + j], sinvl[h], w);
        float u = w * prow[j];
        brow[j] = u;
        lsum += u;
    }
    lsum = blockReduceSum256(lsum, sm);
    if (threadIdx.x == 0) rowsum[blockIdx.x] = lsum;
}

// ---------------------------------------------------------------------------
extern "C" void kernel_launch(void* const* d_in, const int* in_sizes, int n_in,
                              void* d_out, int out_size)
{
    const float* x        = (const float*)d_in[0];
    const float* ln1_w    = (const float*)d_in[1];
    const float* ln1_b    = (const float*)d_in[2];
    const float* in_w     = (const float*)d_in[3];
    const float* in_b     = (const float*)d_in[4];
    const float* phase_w  = (const float*)d_in[5];
    const float* alpha    = (const float*)d_in[6];
    const float* ff_w1    = (const float*)d_in[7];
    const float* ff_b1    = (const float*)d_in[8];
    const float* ff_w2    = (const float*)d_in[9];
    const float* ff_b2    = (const float*)d_in[10];
    const float* ln2_w    = (const float*)d_in[11];
    const float* ln2_b    = (const float*)d_in[12];
    float* out            = (float*)d_out;

    float *xn, *qk, *phase, *scores, *ssum, *pcv, *blend, *rowsum, *xmid, *x2, *hbuf;
    cudaGetSymbolAddress((void**)&xn,     g_xn);
    cudaGetSymbolAddress((void**)&qk,     g_qk);
    cudaGetSymbolAddress((void**)&phase,  g_phase);
    cudaGetSymbolAddress((void**)&scores, g_scores);
    cudaGetSymbolAddress((void**)&ssum,   g_ssum);
    cudaGetSymbolAddress((void**)&pcv,    g_pc);
    cudaGetSymbolAddress((void**)&blend,  g_blend);
    cudaGetSymbolAddress((void**)&rowsum, g_rowsum);
    cudaGetSymbolAddress((void**)&xmid,   g_xmid);
    cudaGetSymbolAddress((void**)&x2,     g_x2);
    cudaGetSymbolAddress((void**)&hbuf,   g_hbuf);

    // 1) xn = LN1(x); zero per-head sums
    ln_kernel<<<NROW, 256>>>(x, ln1_w, ln1_b, xn);
    zero_kernel<<<(BB*NH*SEQ + 255)/256, 256>>>(ssum, BB*NH*SEQ);

    // 2) qk = xn @ W[0:1536]^T + b           [4096, 1536]
    gemm128<true, 1><<<dim3(NROW/128, 1536/128, 1), 256>>>(
        xn, in_w, qk, NROW, 2*DIM, DIM, DIM, DIM, 2*DIM,
        1, 0,0, 0,0, 0,0, 1.0f, in_b, nullptr, 0, nullptr, 0, nullptr, nullptr);

    // 3) phase = tanh(xn @ phase_w^T)        [4096, 64]
    phase_gemm<<<NROW/128, 256>>>(xn, phase_w, phase);

    // 4) scores e = exp(0.125 * q@k^T) + atomic row sums    24 x [2048,2048]
    gemm128<true, 6><<<dim3(SEQ/128, SEQ/128, BB*NH), 256>>>(
        qk, qk + DIM, scores, SEQ, SEQ, DHD, 2*DIM, 2*DIM, SEQ,
        NH, (long)SEQ*2*DIM, (long)DHD, (long)SEQ*2*DIM, (long)DHD,
            (long)NH*SEQ*SEQ, (long)SEQ*SEQ,
        0.125f, nullptr, nullptr, 0, nullptr, 0, nullptr, ssum);

    // 5) pcexp = exp(0.5*alpha*(phase@phase^T) + 0.5*alpha)  2 x [2048,2048]
    gemm128<true, 7><<<dim3(SEQ/128, SEQ/128, BB), 256>>>(
        phase, phase, pcv, SEQ, SEQ, PDIM, PDIM, PDIM, SEQ,
        1, (long)SEQ*PDIM, 0, (long)SEQ*PDIM, 0, (long)SEQ*SEQ, 0,
        1.0f, nullptr, nullptr, 0, nullptr, 0, alpha, nullptr);

    // 6) blend weights + row sums
    blend_kernel<<<BB*SEQ, 256>>>(scores, ssum, pcv, blend, rowsum);

    // 7) xmid = x + (blend/rowsum) @ xn       2 x [2048, 768]
    gemm128<false, 5><<<dim3(SEQ/128, DIM/128, BB), 256>>>(
        blend, xn, xmid, SEQ, DIM, SEQ, SEQ, DIM, DIM,
        1, (long)SEQ*SEQ, 0, (long)SEQ*DIM, 0, (long)SEQ*DIM, 0,
        1.0f, nullptr, x, (long)SEQ*DIM, rowsum, (long)SEQ, nullptr, nullptr);

    // 8) x2 = LN2(xmid)
    ln_kernel<<<NROW, 256>>>(xmid, ln2_w, ln2_b, x2);

    // 9) h = gelu(x2 @ ff_w1^T + b1)          [4096, 3072]
    gemm128<true, 3><<<dim3(NROW/128, FFD/128, 1), 256>>>(
        x2, ff_w1, hbuf, NROW, FFD, DIM, DIM, DIM, FFD,
        1, 0,0, 0,0, 0,0, 1.0f, ff_b1, nullptr, 0, nullptr, 0, nullptr, nullptr);

    // 10) out = xmid + h @ ff_w2^T + b2       [4096, 768]
    gemm128<true, 4><<<dim3(NROW/128, DIM/128, 1), 256>>>(
        hbuf, ff_w2, out, NROW, DIM, FFD, FFD, FFD, DIM,
        1, 0,0, 0,0, 0,0, 1.0f, ff_b2, xmid, 0, nullptr, 0, nullptr, nullptr);

    (void)in_sizes; (void)n_in; (void)out_size;
}

// round 3
// speedup vs baseline: 1.1134x; 1.1134x over previous
#include <cuda_runtime.h>
#include <math.h>

// Problem dims (fixed by the reference)
#define BB   2
#define SEQ  2048
#define DIM  768
#define NH   12
#define DHD  64
#define FFD  3072
#define PDIM 64
#define NROW (BB*SEQ)      // 4096

// ---------------- scratch (device globals; no cudaMalloc allowed) ----------
__device__ __align__(16) float g_xn[NROW*DIM];
__device__ __align__(16) float g_qk[NROW*2*DIM];
__device__ __align__(16) float g_phase[NROW*PDIM];
__device__ __align__(16) float g_scores[(size_t)BB*NH*SEQ*SEQ];   // exp(s/8)
__device__              float g_ssum[BB*NH*SEQ];                  // per-head row sums
__device__ __align__(16) float g_pc[(size_t)BB*SEQ*SEQ];          // exp(a*(pc+1)/2)
__device__ __align__(16) float g_blend[(size_t)BB*SEQ*SEQ];
__device__              float g_rowsum[BB*SEQ];
__device__ __align__(16) float g_xmid[NROW*DIM];
__device__ __align__(16) float g_x2[NROW*DIM];
__device__ __align__(16) float g_hbuf[NROW*FFD];

// ---------------- misc helpers ----------------------------------------------
__device__ __forceinline__ float warpReduceSum(float v) {
#pragma unroll
    for (int o = 16; o > 0; o >>= 1) v += __shfl_xor_sync(0xffffffffu, v, o);
    return v;
}
__device__ __forceinline__ float blockReduceSum256(float v, float* sm) {
    v = warpReduceSum(v);
    if ((threadIdx.x & 31) == 0) sm[threadIdx.x >> 5] = v;
    __syncthreads();
    if (threadIdx.x < 32) {
        float t = (threadIdx.x < 8) ? sm[threadIdx.x] : 0.0f;
        t = warpReduceSum(t);
        if (threadIdx.x == 0) sm[0] = t;
    }
    __syncthreads();
    float r = sm[0];
    __syncthreads();
    return r;
}

// Fast exp on the FMA pipe (no MUFU). Max rel err ~3e-6.
__device__ __forceinline__ float fast_exp(float x) {
    x = fmaxf(x, -87.0f);
    float y  = x * 1.4426950408889634f;
    float z  = y + 12582912.0f;                 // 1.5 * 2^23
    float nf = z - 12582912.0f;
    float f  = y - nf;
    float p  = 1.3333558146e-3f;
    p = fmaf(p, f, 9.6181291076e-3f);
    p = fmaf(p, f, 5.5504108665e-2f);
    p = fmaf(p, f, 2.4022650696e-1f);
    p = fmaf(p, f, 6.9314718056e-1f);
    p = fmaf(p, f, 1.0f);
    unsigned sb = ((unsigned)__float_as_int(z) + (unsigned)(127 - 0x4B400000)) << 23;
    return p * __int_as_float(sb);
}

// ---------------- LayerNorm ------------------------------------------------
__global__ void __launch_bounds__(256) ln_kernel(
    const float* __restrict__ x, const float* __restrict__ w,
    const float* __restrict__ b, float* __restrict__ o)
{
    __shared__ float sm[8];
    const float* xr = x + (size_t)blockIdx.x * DIM;
    int t = threadIdx.x;
    float v0 = xr[t], v1 = xr[t + 256], v2 = xr[t + 512];
    float mean = blockReduceSum256(v0 + v1 + v2, sm) * (1.0f / DIM);
    float d0 = v0 - mean, d1 = v1 - mean, d2 = v2 - mean;
    float var = blockReduceSum256(d0*d0 + d1*d1 + d2*d2, sm) * (1.0f / DIM);
    float r = rsqrtf(var + 1e-5f);
    float* orow = o + (size_t)blockIdx.x * DIM;
    orow[t      ] = d0 * r * w[t      ] + b[t      ];
    orow[t + 256] = d1 * r * w[t + 256] + b[t + 256];
    orow[t + 512] = d2 * r * w[t + 512] + b[t + 512];
}

__global__ void __launch_bounds__(256) zero_kernel(float* __restrict__ p, int n) {
    int i = blockIdx.x * 256 + threadIdx.x;
    if (i < n) p[i] = 0.0f;
}

// ============================================================================
// 128x128x16 SGEMM, plain FFMA, double-buffered smem + register prefetch.
// 256 threads, TM=8, TN=8.
// TRB=true : B row-major [N,K] -> C = A@B^T ; TRB=false: B [K,N] -> C = A@B.
// EPI: 1=+bias, 3=bias+exact GELU, 4=bias+residual,
//      5=row-divide(rowsum)+residual, 6=exp(scale*v)+atomic rowsum,
//      7=exp(a2*v + a2) with a2 = 0.5*alpha   (phase coherence)
// ============================================================================
template<bool TRB, int EPI>
__global__ void __launch_bounds__(256, 2) gemm128(
    const float* __restrict__ A, const float* __restrict__ Bm,
    float* __restrict__ C,
    int M, int N, int K, int lda, int ldb, int ldc,
    int zdiv,
    long as1, long as2, long bs1, long bs2, long cs1, long cs2,
    float scale,
    const float* __restrict__ bias,
    const float* __restrict__ res, long ress1,
    const float* __restrict__ rsum, long rsums1,
    const float* __restrict__ alphap,
    float* __restrict__ ssum)
{
    const int BM = 128, BN = 128, BK = 16;
    int z = blockIdx.z;
    int z1 = z / zdiv, z2 = z - z1 * zdiv;
    A  += z1 * as1 + z2 * as2;
    Bm += z1 * bs1 + z2 * bs2;
    C  += z1 * cs1 + z2 * cs2;
    if (EPI == 4 || EPI == 5) res  += z1 * ress1;
    if (EPI == 5)             rsum += z1 * rsums1;
    if (EPI == 6)             ssum += (size_t)z * M;

    __shared__ float As[2][BK][BM + 4];
    __shared__ float Bs[2][BK][BN + 4];

    int tid = threadIdx.x;
    int tx = tid & 15, ty = tid >> 4;
    int bm = blockIdx.x * BM, bn = blockIdx.y * BN;

    float acc[8][8];
#pragma unroll
    for (int i = 0; i < 8; i++)
#pragma unroll
        for (int j = 0; j < 8; j++) acc[i][j] = 0.0f;

    const float* Ab = A + (size_t)bm * lda;

    int ra = tid >> 2, ca = (tid & 3) << 2;        // A / B(TRB) staging coords
    int rb2 = tid >> 5, cb2 = (tid & 31) << 2;     // B(!TRB) staging coords

    float4 sA0, sA1, sB0, sB1;
    // ---- stage tile k0=0 into regs, commit to buffer 0 ----
    sA0 = *(const float4*)(Ab + (size_t)ra * lda + ca);
    sA1 = *(const float4*)(Ab + (size_t)(ra + 64) * lda + ca);
    if (TRB) {
        sB0 = *(const float4*)(Bm + (size_t)(bn + ra) * ldb + ca);
        sB1 = *(const float4*)(Bm + (size_t)(bn + ra + 64) * ldb + ca);
    } else {
        sB0 = *(const float4*)(Bm + (size_t)rb2 * ldb + (bn + cb2));
        sB1 = *(const float4*)(Bm + (size_t)(rb2 + 8) * ldb + (bn + cb2));
    }
    As[0][ca + 0][ra] = sA0.x; As[0][ca + 1][ra] = sA0.y;
    As[0][ca + 2][ra] = sA0.z; As[0][ca + 3][ra] = sA0.w;
    As[0][ca + 0][ra + 64] = sA1.x; As[0][ca + 1][ra + 64] = sA1.y;
    As[0][ca + 2][ra + 64] = sA1.z; As[0][ca + 3][ra + 64] = sA1.w;
    if (TRB) {
        Bs[0][ca + 0][ra] = sB0.x; Bs[0][ca + 1][ra] = sB0.y;
        Bs[0][ca + 2][ra] = sB0.z; Bs[0][ca + 3][ra] = sB0.w;
        Bs[0][ca + 0][ra + 64] = sB1.x; Bs[0][ca + 1][ra + 64] = sB1.y;
        Bs[0][ca + 2][ra + 64] = sB1.z; Bs[0][ca + 3][ra + 64] = sB1.w;
    } else {
        *(float4*)&Bs[0][rb2][cb2]     = sB0;
        *(float4*)&Bs[0][rb2 + 8][cb2] = sB1;
    }
    __syncthreads();

    int buf = 0;
    for (int k0 = 0; k0 < K; k0 += BK) {
        int kn = k0 + BK;
        // prefetch next tile's global loads into registers
        if (kn < K) {
            sA0 = *(const float4*)(Ab + (size_t)ra * lda + (kn + ca));
            sA1 = *(const float4*)(Ab + (size_t)(ra + 64) * lda + (kn + ca));
            if (TRB) {
                sB0 = *(const float4*)(Bm + (size_t)(bn + ra) * ldb + (kn + ca));
                sB1 = *(const float4*)(Bm + (size_t)(bn + ra + 64) * ldb + (kn + ca));
            } else {
                sB0 = *(const float4*)(Bm + (size_t)(kn + rb2) * ldb + (bn + cb2));
                sB1 = *(const float4*)(Bm + (size_t)(kn + rb2 + 8) * ldb + (bn + cb2));
            }
        }

        // compute on current buffer
#pragma unroll
        for (int kk = 0; kk < BK; kk++) {
            float af[8], bf[8];
            *(float4*)&af[0] = *(const float4*)&As[buf][kk][ty * 8];
            *(float4*)&af[4] = *(const float4*)&As[buf][kk][ty * 8 + 4];
            *(float4*)&bf[0] = *(const float4*)&Bs[buf][kk][tx * 8];
            *(float4*)&bf[4] = *(const float4*)&Bs[buf][kk][tx * 8 + 4];
#pragma unroll
            for (int i = 0; i < 8; i++)
#pragma unroll
                for (int j = 0; j < 8; j++)
                    acc[i][j] = fmaf(af[i], bf[j], acc[i][j]);
        }

        // commit next tile into the other buffer
        if (kn < K) {
            int nb = buf ^ 1;
            As[nb][ca + 0][ra] = sA0.x; As[nb][ca + 1][ra] = sA0.y;
            As[nb][ca + 2][ra] = sA0.z; As[nb][ca + 3][ra] = sA0.w;
            As[nb][ca + 0][ra + 64] = sA1.x; As[nb][ca + 1][ra + 64] = sA1.y;
            As[nb][ca + 2][ra + 64] = sA1.z; As[nb][ca + 3][ra + 64] = sA1.w;
            if (TRB) {
                Bs[nb][ca + 0][ra] = sB0.x; Bs[nb][ca + 1][ra] = sB0.y;
                Bs[nb][ca + 2][ra] = sB0.z; Bs[nb][ca + 3][ra] = sB0.w;
                Bs[nb][ca + 0][ra + 64] = sB1.x; Bs[nb][ca + 1][ra + 64] = sB1.y;
                Bs[nb][ca + 2][ra + 64] = sB1.z; Bs[nb][ca + 3][ra + 64] = sB1.w;
            } else {
                *(float4*)&Bs[nb][rb2][cb2]     = sB0;
                *(float4*)&Bs[nb][rb2 + 8][cb2] = sB1;
            }
            __syncthreads();
            buf = nb;
        }
    }

    // ---------------- epilogue ----------------
    float a2v = 0.0f;
    if (EPI == 7) a2v = 0.5f * (*alphap);
    int n0 = bn + tx * 8;
    int lane = tid & 31;

#pragma unroll
    for (int i = 0; i < 8; i++) {
        int m = bm + ty * 8 + i;
        float rinv = 0.0f;
        if (EPI == 5) rinv = 1.0f / rsum[m];
        float vv[8];
#pragma unroll
        for (int j = 0; j < 8; j++) {
            float v = acc[i][j];
            int n = n0 + j;
            if (EPI == 1) v += bias[n];
            if (EPI == 3) { v += bias[n]; v = 0.5f * v * (1.0f + erff(v * 0.70710678118654752f)); }
            if (EPI == 4) { v = v + bias[n] + res[(size_t)m * ldc + n]; }
            if (EPI == 5) { v = v * rinv + res[(size_t)m * ldc + n]; }
            if (EPI == 6) { v = fast_exp(v * scale); }
            if (EPI == 7) { v = fast_exp(fmaf(v, a2v, a2v)); }
            vv[j] = v;
        }
        if (EPI == 6) {
            float rs = 0.0f;
#pragma unroll
            for (int j = 0; j < 8; j++) rs += vv[j];
#pragma unroll
            for (int o = 8; o > 0; o >>= 1) rs += __shfl_xor_sync(0xffffffffu, rs, o);
            if ((lane & 15) == 0) atomicAdd(&ssum[m], rs);
        }
        float4 o0; o0.x = vv[0]; o0.y = vv[1]; o0.z = vv[2]; o0.w = vv[3];
        float4 o1; o1.x = vv[4]; o1.y = vv[5]; o1.z = vv[6]; o1.w = vv[7];
        *(float4*)(C + (size_t)m * ldc + n0)     = o0;
        *(float4*)(C + (size_t)m * ldc + n0 + 4) = o1;
    }
}

// ---------------- small GEMM for phase (N=64): C = tanh(A @ B^T) ------------
__global__ void __launch_bounds__(256) phase_gemm(
    const float* __restrict__ A, const float* __restrict__ Bm,
    float* __restrict__ C)
{
    const int BM = 128, BN = 64, BK = 16, TM = 8, TN = 4;
    __shared__ float As[BK][BM + 4];
    __shared__ float Bs[BK][BN + 4];
    int tid = threadIdx.x;
    int tx = tid & 15, ty = tid >> 4;
    int bm = blockIdx.x * BM;
    float acc[TM][TN];
#pragma unroll
    for (int i = 0; i < TM; i++)
#pragma unroll
        for (int j = 0; j < TN; j++) acc[i][j] = 0.0f;
    const float* Ab = A + (size_t)bm * DIM;
    for (int k0 = 0; k0 < DIM; k0 += BK) {
#pragma unroll
        for (int i = 0; i < 2; i++) {
            int id = tid + i * 256;
            int r = id >> 2, c = (id & 3) << 2;
            const float4 v = *(const float4*)(Ab + (size_t)r * DIM + (k0 + c));
            As[c + 0][r] = v.x; As[c + 1][r] = v.y;
            As[c + 2][r] = v.z; As[c + 3][r] = v.w;
        }
        {
            int r = tid >> 2, c = (tid & 3) << 2;
            const float4 v = *(const float4*)(Bm + (size_t)r * DIM + (k0 + c));
            Bs[c + 0][r] = v.x; Bs[c + 1][r] = v.y;
            Bs[c + 2][r] = v.z; Bs[c + 3][r] = v.w;
        }
        __syncthreads();
#pragma unroll
        for (int kk = 0; kk < BK; kk++) {
            float af[TM], bf[TN];
            *(float4*)&af[0] = *(const float4*)&As[kk][ty * TM];
            *(float4*)&af[4] = *(const float4*)&As[kk][ty * TM + 4];
            *(float4*)&bf[0] = *(const float4*)&Bs[kk][tx * TN];
#pragma unroll
            for (int i = 0; i < TM; i++)
#pragma unroll
                for (int j = 0; j < TN; j++)
                    acc[i][j] = fmaf(af[i], bf[j], acc[i][j]);
        }
        __syncthreads();
    }
#pragma unroll
    for (int i = 0; i < TM; i++) {
        int m = bm + ty * TM + i;
        int n0 = tx * TN;
        float4 o;
        o.x = tanhf(acc[i][0]); o.y = tanhf(acc[i][1]);
        o.z = tanhf(acc[i][2]); o.w = tanhf(acc[i][3]);
        *(float4*)(C + (size_t)m * PDIM + n0) = o;
    }
}

// --------- blend: u = (mean_h softmax_h + 1e-6) * pcexp; rowsum -------------
__global__ void __launch_bounds__(256) blend_kernel(
    const float* __restrict__ scoresE, const float* __restrict__ ssum,
    const float* __restrict__ pcexp, float* __restrict__ blend,
    float* __restrict__ rowsum)
{
    __shared__ float sm[8];
    __shared__ float sinvl[NH];
    int b = blockIdx.x / SEQ;
    int i = blockIdx.x - b * SEQ;
    if (threadIdx.x < NH)
        sinvl[threadIdx.x] = 1.0f / (ssum[(b * NH + threadIdx.x) * SEQ + i] * (float)NH);
    __syncthreads();

    const float* ebase = scoresE + ((size_t)(b * NH) * SEQ + (size_t)i) * SEQ;
    const float* prow  = pcexp + ((size_t)b * SEQ + i) * SEQ;
    float*       brow  = blend + ((size_t)b * SEQ + i) * SEQ;

    float lsum = 0.0f;
    for (int j = threadIdx.x; j < SEQ; j += 256) {
        float w = 1e-6f;
#pragma unroll
        for (int h = 0; h < NH; h++)
            w = fmaf(ebase[(size_t)h * SEQ * SEQ + j], sinvl[h], w);
        float u = w * prow[j];
        brow[j] = u;
        lsum += u;
    }
    lsum = blockReduceSum256(lsum, sm);
    if (threadIdx.x == 0) rowsum[blockIdx.x] = lsum;
}

// ---------------------------------------------------------------------------
extern "C" void kernel_launch(void* const* d_in, const int* in_sizes, int n_in,
                              void* d_out, int out_size)
{
    const float* x        = (const float*)d_in[0];
    const float* ln1_w    = (const float*)d_in[1];
    const float* ln1_b    = (const float*)d_in[2];
    const float* in_w     = (const float*)d_in[3];
    const float* in_b     = (const float*)d_in[4];
    const float* phase_w  = (const float*)d_in[5];
    const float* alpha    = (const float*)d_in[6];
    const float* ff_w1    = (const float*)d_in[7];
    const float* ff_b1    = (const float*)d_in[8];
    const float* ff_w2    = (const float*)d_in[9];
    const float* ff_b2    = (const float*)d_in[10];
    const float* ln2_w    = (const float*)d_in[11];
    const float* ln2_b    = (const float*)d_in[12];
    float* out            = (float*)d_out;

    float *xn, *qk, *phase, *scores, *ssum, *pcv, *blend, *rowsum, *xmid, *x2, *hbuf;
    cudaGetSymbolAddress((void**)&xn,     g_xn);
    cudaGetSymbolAddress((void**)&qk,     g_qk);
    cudaGetSymbolAddress((void**)&phase,  g_phase);
    cudaGetSymbolAddress((void**)&scores, g_scores);
    cudaGetSymbolAddress((void**)&ssum,   g_ssum);
    cudaGetSymbolAddress((void**)&pcv,    g_pc);
    cudaGetSymbolAddress((void**)&blend,  g_blend);
    cudaGetSymbolAddress((void**)&rowsum, g_rowsum);
    cudaGetSymbolAddress((void**)&xmid,   g_xmid);
    cudaGetSymbolAddress((void**)&x2,     g_x2);
    cudaGetSymbolAddress((void**)&hbuf,   g_hbuf);

    // 1) xn = LN1(x); zero per-head sums
    ln_kernel<<<NROW, 256>>>(x, ln1_w, ln1_b, xn);
    zero_kernel<<<(BB*NH*SEQ + 255)/256, 256>>>(ssum, BB*NH*SEQ);

    // 2) qk = xn @ W[0:1536]^T + b           [4096, 1536]
    gemm128<true, 1><<<dim3(NROW/128, 1536/128, 1), 256>>>(
        xn, in_w, qk, NROW, 2*DIM, DIM, DIM, DIM, 2*DIM,
        1, 0,0, 0,0, 0,0, 1.0f, in_b, nullptr, 0, nullptr, 0, nullptr, nullptr);

    // 3) phase = tanh(xn @ phase_w^T)        [4096, 64]
    phase_gemm<<<NROW/128, 256>>>(xn, phase_w, phase);

    // 4) scores e = exp(0.125 * q@k^T) + atomic row sums    24 x [2048,2048]
    gemm128<true, 6><<<dim3(SEQ/128, SEQ/128, BB*NH), 256>>>(
        qk, qk + DIM, scores, SEQ, SEQ, DHD, 2*DIM, 2*DIM, SEQ,
        NH, (long)SEQ*2*DIM, (long)DHD, (long)SEQ*2*DIM, (long)DHD,
            (long)NH*SEQ*SEQ, (long)SEQ*SEQ,
        0.125f, nullptr, nullptr, 0, nullptr, 0, nullptr, ssum);

    // 5) pcexp = exp(0.5*alpha*(phase@phase^T) + 0.5*alpha)  2 x [2048,2048]
    gemm128<true, 7><<<dim3(SEQ/128, SEQ/128, BB), 256>>>(
        phase, phase, pcv, SEQ, SEQ, PDIM, PDIM, PDIM, SEQ,
        1, (long)SEQ*PDIM, 0, (long)SEQ*PDIM, 0, (long)SEQ*SEQ, 0,
        1.0f, nullptr, nullptr, 0, nullptr, 0, alpha, nullptr);

    // 6) blend weights + row sums
    blend_kernel<<<BB*SEQ, 256>>>(scores, ssum, pcv, blend, rowsum);

    // 7) xmid = x + (blend/rowsum) @ xn       2 x [2048, 768]
    gemm128<false, 5><<<dim3(SEQ/128, DIM/128, BB), 256>>>(
        blend, xn, xmid, SEQ, DIM, SEQ, SEQ, DIM, DIM,
        1, (long)SEQ*SEQ, 0, (long)SEQ*DIM, 0, (long)SEQ*DIM, 0,
        1.0f, nullptr, x, (long)SEQ*DIM, rowsum, (long)SEQ, nullptr, nullptr);

    // 8) x2 = LN2(xmid)
    ln_kernel<<<NROW, 256>>>(xmid, ln2_w, ln2_b, x2);

    // 9) h = gelu(x2 @ ff_w1^T + b1)          [4096, 3072]
    gemm128<true, 3><<<dim3(NROW/128, FFD/128, 1), 256>>>(
        x2, ff_w1, hbuf, NROW, FFD, DIM, DIM, DIM, FFD,
        1, 0,0, 0,0, 0,0, 1.0f, ff_b1, nullptr, 0, nullptr, 0, nullptr, nullptr);

    // 10) out = xmid + h @ ff_w2^T + b2       [4096, 768]
    gemm128<true, 4><<<dim3(NROW/128, DIM/128, 1), 256>>>(
        hbuf, ff_w2, out, NROW, DIM, FFD, FFD, FFD, DIM,
        1, 0,0, 0,0, 0,0, 1.0f, ff_b2, xmid, 0, nullptr, 0, nullptr, nullptr);

    (void)in_sizes; (void)n_in; (void)out_size;
}

// round 4
// speedup vs baseline: 2.3054x; 2.0707x over previous
#include <cuda_runtime.h>
#include <math.h>

// Problem dims (fixed by the reference)
#define BB   2
#define SEQ  2048
#define DIM  768
#define NH   12
#define DHD  64
#define FFD  3072
#define PDIM 64
#define PDPAD 128
#define NROW (BB*SEQ)      // 4096

// ---------------- scratch (device globals; no cudaMalloc allowed) ----------
__device__ __align__(16) float g_xn[NROW*DIM];
__device__ __align__(16) float g_qk[NROW*2*DIM];
__device__ __align__(16) float g_phw[PDPAD*DIM];                  // padded phase_w
__device__ __align__(16) float g_phase[NROW*PDPAD];               // padded phase
__device__ __align__(16) float g_scores[(size_t)BB*NH*SEQ*SEQ];   // exp(s/8)
__device__              float g_ssum[BB*NH*SEQ];
__device__ __align__(16) float g_pc[(size_t)BB*SEQ*SEQ];          // exp(a*(pc+1)/2)
__device__ __align__(16) float g_blend[(size_t)BB*SEQ*SEQ];
__device__              float g_rowsum[BB*SEQ];
__device__ __align__(16) float g_xmid[NROW*DIM];
__device__ __align__(16) float g_x2[NROW*DIM];
__device__ __align__(16) float g_hbuf[NROW*FFD];

// ---------------- helpers ----------------------------------------------------
__device__ __forceinline__ float warpReduceSum(float v) {
#pragma unroll
    for (int o = 16; o > 0; o >>= 1) v += __shfl_xor_sync(0xffffffffu, v, o);
    return v;
}
__device__ __forceinline__ float blockReduceSum256(float v, float* sm) {
    v = warpReduceSum(v);
    if ((threadIdx.x & 31) == 0) sm[threadIdx.x >> 5] = v;
    __syncthreads();
    if (threadIdx.x < 32) {
        float t = (threadIdx.x < 8) ? sm[threadIdx.x] : 0.0f;
        t = warpReduceSum(t);
        if (threadIdx.x == 0) sm[0] = t;
    }
    __syncthreads();
    float r = sm[0];
    __syncthreads();
    return r;
}

// Fast exp on the FMA pipe. Max rel err ~3e-6.
__device__ __forceinline__ float fast_exp(float x) {
    x = fmaxf(x, -87.0f);
    float y  = x * 1.4426950408889634f;
    float z  = y + 12582912.0f;
    float nf = z - 12582912.0f;
    float f  = y - nf;
    float p  = 1.3333558146e-3f;
    p = fmaf(p, f, 9.6181291076e-3f);
    p = fmaf(p, f, 5.5504108665e-2f);
    p = fmaf(p, f, 2.4022650696e-1f);
    p = fmaf(p, f, 6.9314718056e-1f);
    p = fmaf(p, f, 1.0f);
    unsigned sb = ((unsigned)__float_as_int(z) + (unsigned)(127 - 0x4B400000)) << 23;
    return p * __int_as_float(sb);
}

__device__ __forceinline__ unsigned cvt_tf32(float x) {
    unsigned r;
    asm("cvt.rna.tf32.f32 %0, %1;" : "=r"(r) : "f"(x));
    return r;
}
__device__ __forceinline__ void mma_tf32(float* c, const unsigned* a, const unsigned* b) {
    asm("mma.sync.aligned.m16n8k8.row.col.f32.tf32.tf32.f32 "
        "{%0,%1,%2,%3}, {%4,%5,%6,%7}, {%8,%9}, {%0,%1,%2,%3};"
        : "+f"(c[0]), "+f"(c[1]), "+f"(c[2]), "+f"(c[3])
        : "r"(a[0]), "r"(a[1]), "r"(a[2]), "r"(a[3]), "r"(b[0]), "r"(b[1]));
}

// ---------------- LayerNorm ------------------------------------------------
__global__ void __launch_bounds__(256) ln_kernel(
    const float* __restrict__ x, const float* __restrict__ w,
    const float* __restrict__ b, float* __restrict__ o)
{
    __shared__ float sm[8];
    const float* xr = x + (size_t)blockIdx.x * DIM;
    int t = threadIdx.x;
    float v0 = xr[t], v1 = xr[t + 256], v2 = xr[t + 512];
    float mean = blockReduceSum256(v0 + v1 + v2, sm) * (1.0f / DIM);
    float d0 = v0 - mean, d1 = v1 - mean, d2 = v2 - mean;
    float var = blockReduceSum256(d0*d0 + d1*d1 + d2*d2, sm) * (1.0f / DIM);
    float r = rsqrtf(var + 1e-5f);
    float* orow = o + (size_t)blockIdx.x * DIM;
    orow[t      ] = d0 * r * w[t      ] + b[t      ];
    orow[t + 256] = d1 * r * w[t + 256] + b[t + 256];
    orow[t + 512] = d2 * r * w[t + 512] + b[t + 512];
}

__global__ void __launch_bounds__(256) zero_kernel(float* __restrict__ p, int n) {
    int i = blockIdx.x * 256 + threadIdx.x;
    if (i < n) p[i] = 0.0f;
}

// pad phase_w [64,768] -> [128,768] with zeros
__global__ void __launch_bounds__(256) pad_phw_kernel(
    const float* __restrict__ w, float* __restrict__ o)
{
    int i = blockIdx.x * 256 + threadIdx.x;
    if (i < PDPAD * DIM) o[i] = (i < PDIM * DIM) ? w[i] : 0.0f;
}

// ============================================================================
// tf32 tensor-core GEMM: 128x128x16 CTA tile, 8 warps (2x4), warp 64x32,
// mma.sync m16n8k8, double-buffered smem, cvt.rna.tf32 at staging.
// TRB=true : B row-major [N,K] -> C = A@B^T ; TRB=false: B [K,N] -> C = A@B.
// EPI: 1=+bias, 2=tanh, 3=bias+exact GELU, 4=bias+residual,
//      5=row-divide(rowsum)+residual, 6=exp(scale*v)+atomic rowsum,
//      7=exp(a2*v + a2), a2 = 0.5*alpha
// ============================================================================
template<bool TRB, int EPI>
__global__ void __launch_bounds__(256) tgemm(
    const float* __restrict__ A, const float* __restrict__ Bm,
    float* __restrict__ C,
    int M, int N, int K, int lda, int ldb, int ldc,
    int zdiv,
    long as1, long as2, long bs1, long bs2, long cs1, long cs2,
    float scale,
    const float* __restrict__ bias,
    const float* __restrict__ res, long ress1,
    const float* __restrict__ rsum, long rsums1,
    const float* __restrict__ alphap,
    float* __restrict__ ssum)
{
    const int BK = 16;
    int z = blockIdx.z;
    int z1 = z / zdiv, z2 = z - z1 * zdiv;
    A  += z1 * as1 + z2 * as2;
    Bm += z1 * bs1 + z2 * bs2;
    C  += z1 * cs1 + z2 * cs2;
    if (EPI == 4 || EPI == 5) res  += z1 * ress1;
    if (EPI == 5)             rsum += z1 * rsums1;
    if (EPI == 6)             ssum += (size_t)z * M;

    // [buf][row(m or n)][k], pad 20 for conflict-free fragment loads
    __shared__ unsigned As[2][128][20];
    __shared__ unsigned Bs[2][128][20];

    int tid  = threadIdx.x;
    int lane = tid & 31;
    int wid  = tid >> 5;
    int wm   = (wid & 1) * 64;     // warp row base in tile
    int wn   = (wid >> 1) * 32;    // warp col base in tile
    int g    = lane >> 2;          // group id 0..7
    int tg   = lane & 3;           // thread in group 0..3
    int bm = blockIdx.x * 128, bn = blockIdx.y * 128;

    float acc[4][4][4];
#pragma unroll
    for (int i = 0; i < 4; i++)
#pragma unroll
        for (int j = 0; j < 4; j++)
#pragma unroll
            for (int r = 0; r < 4; r++) acc[i][j][r] = 0.0f;

    const float* Ab = A + (size_t)bm * lda;

    // staging coords
    int ra = tid >> 2, fa = (tid & 3) << 2;         // A rows / B(TRB) rows
    int kr = tid >> 5, nc = (tid & 31) << 2;        // B(!TRB): kr 0..7 (x2), nc col

    float4 sA0, sA1, sB0, sB1;
    // ---- load tile k0=0 ----
    sA0 = *(const float4*)(Ab + (size_t)ra * lda + fa);
    sA1 = *(const float4*)(Ab + (size_t)(ra + 64) * lda + fa);
    if (TRB) {
        sB0 = *(const float4*)(Bm + (size_t)(bn + ra) * ldb + fa);
        sB1 = *(const float4*)(Bm + (size_t)(bn + ra + 64) * ldb + fa);
    } else {
        sB0 = *(const float4*)(Bm + (size_t)kr * ldb + (bn + nc));
        sB1 = *(const float4*)(Bm + (size_t)(kr + 8) * ldb + (bn + nc));
    }

    auto commit = [&](int buf, const float4& a0, const float4& a1,
                      const float4& b0, const float4& b1) {
        uint4 ca0 = {cvt_tf32(a0.x), cvt_tf32(a0.y), cvt_tf32(a0.z), cvt_tf32(a0.w)};
        uint4 ca1 = {cvt_tf32(a1.x), cvt_tf32(a1.y), cvt_tf32(a1.z), cvt_tf32(a1.w)};
        *(uint4*)&As[buf][ra][fa]      = ca0;
        *(uint4*)&As[buf][ra + 64][fa] = ca1;
        if (TRB) {
            uint4 cb0 = {cvt_tf32(b0.x), cvt_tf32(b0.y), cvt_tf32(b0.z), cvt_tf32(b0.w)};
            uint4 cb1 = {cvt_tf32(b1.x), cvt_tf32(b1.y), cvt_tf32(b1.z), cvt_tf32(b1.w)};
            *(uint4*)&Bs[buf][ra][fa]      = cb0;
            *(uint4*)&Bs[buf][ra + 64][fa] = cb1;
        } else {
            Bs[buf][nc + 0][kr] = cvt_tf32(b0.x);
            Bs[buf][nc + 1][kr] = cvt_tf32(b0.y);
            Bs[buf][nc + 2][kr] = cvt_tf32(b0.z);
            Bs[buf][nc + 3][kr] = cvt_tf32(b0.w);
            Bs[buf][nc + 0][kr + 8] = cvt_tf32(b1.x);
            Bs[buf][nc + 1][kr + 8] = cvt_tf32(b1.y);
            Bs[buf][nc + 2][kr + 8] = cvt_tf32(b1.z);
            Bs[buf][nc + 3][kr + 8] = cvt_tf32(b1.w);
        }
    };

    commit(0, sA0, sA1, sB0, sB1);
    __syncthreads();

    int buf = 0;
    for (int k0 = 0; k0 < K; k0 += BK) {
        int kn = k0 + BK;
        if (kn < K) {
            sA0 = *(const float4*)(Ab + (size_t)ra * lda + (kn + fa));
            sA1 = *(const float4*)(Ab + (size_t)(ra + 64) * lda + (kn + fa));
            if (TRB) {
                sB0 = *(const float4*)(Bm + (size_t)(bn + ra) * ldb + (kn + fa));
                sB1 = *(const float4*)(Bm + (size_t)(bn + ra + 64) * ldb + (kn + fa));
            } else {
                sB0 = *(const float4*)(Bm + (size_t)(kn + kr) * ldb + (bn + nc));
                sB1 = *(const float4*)(Bm + (size_t)(kn + kr + 8) * ldb + (bn + nc));
            }
        }

#pragma unroll
        for (int ks = 0; ks < 2; ks++) {
            int kb = ks * 8 + tg;
            unsigned afr[4][4], bfr[4][2];
#pragma unroll
            for (int mt = 0; mt < 4; mt++) {
                int row = wm + mt * 16 + g;
                afr[mt][0] = As[buf][row][kb];
                afr[mt][1] = As[buf][row + 8][kb];
                afr[mt][2] = As[buf][row][kb + 4];
                afr[mt][3] = As[buf][row + 8][kb + 4];
            }
#pragma unroll
            for (int nt = 0; nt < 4; nt++) {
                int col = wn + nt * 8 + g;
                bfr[nt][0] = Bs[buf][col][kb];
                bfr[nt][1] = Bs[buf][col][kb + 4];
            }
#pragma unroll
            for (int mt = 0; mt < 4; mt++)
#pragma unroll
                for (int nt = 0; nt < 4; nt++)
                    mma_tf32(acc[mt][nt], afr[mt], bfr[nt]);
        }

        if (kn < K) {
            int nb = buf ^ 1;
            commit(nb, sA0, sA1, sB0, sB1);
            __syncthreads();
            buf = nb;
        }
    }

    // ---------------- epilogue ----------------
    float a2v = 0.0f;
    if (EPI == 7) a2v = 0.5f * (*alphap);

#pragma unroll
    for (int mt = 0; mt < 4; mt++) {
#pragma unroll
        for (int half = 0; half < 2; half++) {
            int m = bm + wm + mt * 16 + g + half * 8;
            float rinv = 0.0f;
            if (EPI == 5) rinv = 1.0f / rsum[m];
            float rs = 0.0f;
#pragma unroll
            for (int nt = 0; nt < 4; nt++) {
                int c = bn + wn + nt * 8 + tg * 2;
                float v0 = acc[mt][nt][half * 2];
                float v1 = acc[mt][nt][half * 2 + 1];
                if (EPI == 1) { v0 += bias[c]; v1 += bias[c + 1]; }
                if (EPI == 2) { v0 = tanhf(v0); v1 = tanhf(v1); }
                if (EPI == 3) {
                    v0 += bias[c]; v1 += bias[c + 1];
                    v0 = 0.5f * v0 * (1.0f + erff(v0 * 0.70710678118654752f));
                    v1 = 0.5f * v1 * (1.0f + erff(v1 * 0.70710678118654752f));
                }
                if (EPI == 4) {
                    const float2 rr = *(const float2*)(res + (size_t)m * ldc + c);
                    v0 += bias[c] + rr.x; v1 += bias[c + 1] + rr.y;
                }
                if (EPI == 5) {
                    const float2 rr = *(const float2*)(res + (size_t)m * ldc + c);
                    v0 = v0 * rinv + rr.x; v1 = v1 * rinv + rr.y;
                }
                if (EPI == 6) { v0 = fast_exp(v0 * scale); v1 = fast_exp(v1 * scale); }
                if (EPI == 7) { v0 = fast_exp(fmaf(v0, a2v, a2v)); v1 = fast_exp(fmaf(v1, a2v, a2v)); }
                if (EPI == 6) rs += v0 + v1;
                float2 o; o.x = v0; o.y = v1;
                *(float2*)(C + (size_t)m * ldc + c) = o;
            }
            if (EPI == 6) {
                rs += __shfl_xor_sync(0xffffffffu, rs, 1);
                rs += __shfl_xor_sync(0xffffffffu, rs, 2);
                if (tg == 0) atomicAdd(&ssum[m], rs);
            }
        }
    }
}

// --------- blend: u = (mean_h softmax_h + 1e-6) * pcexp; rowsum -------------
__global__ void __launch_bounds__(256) blend_kernel(
    const float* __restrict__ scoresE, const float* __restrict__ ssum,
    const float* __restrict__ pcexp, float* __restrict__ blend,
    float* __restrict__ rowsum)
{
    __shared__ float sm[8];
    __shared__ float sinvl[NH];
    int b = blockIdx.x / SEQ;
    int i = blockIdx.x - b * SEQ;
    if (threadIdx.x < NH)
        sinvl[threadIdx.x] = 1.0f / (ssum[(b * NH + threadIdx.x) * SEQ + i] * (float)NH);
    __syncthreads();

    const float* ebase = scoresE + ((size_t)(b * NH) * SEQ + (size_t)i) * SEQ;
    const float* prow  = pcexp + ((size_t)b * SEQ + i) * SEQ;
    float*       brow  = blend + ((size_t)b * SEQ + i) * SEQ;

    float lsum = 0.0f;
    for (int j = threadIdx.x; j < SEQ; j += 256) {
        float w = 1e-6f;
#pragma unroll
        for (int h = 0; h < NH; h++)
            w = fmaf(ebase[(size_t)h * SEQ * SEQ + j], sinvl[h], w);
        float u = w * prow[j];
        brow[j] = u;
        lsum += u;
    }
    lsum = blockReduceSum256(lsum, sm);
    if (threadIdx.x == 0) rowsum[blockIdx.x] = lsum;
}

// ---------------------------------------------------------------------------
extern "C" void kernel_launch(void* const* d_in, const int* in_sizes, int n_in,
                              void* d_out, int out_size)
{
    const float* x        = (const float*)d_in[0];
    const float* ln1_w    = (const float*)d_in[1];
    const float* ln1_b    = (const float*)d_in[2];
    const float* in_w     = (const float*)d_in[3];
    const float* in_b     = (const float*)d_in[4];
    const float* phase_w  = (const float*)d_in[5];
    const float* alpha    = (const float*)d_in[6];
    const float* ff_w1    = (const float*)d_in[7];
    const float* ff_b1    = (const float*)d_in[8];
    const float* ff_w2    = (const float*)d_in[9];
    const float* ff_b2    = (const float*)d_in[10];
    const float* ln2_w    = (const float*)d_in[11];
    const float* ln2_b    = (const float*)d_in[12];
    float* out            = (float*)d_out;

    float *xn, *qk, *phw, *phase, *scores, *ssum, *pcv, *blend, *rowsum, *xmid, *x2, *hbuf;
    cudaGetSymbolAddress((void**)&xn,     g_xn);
    cudaGetSymbolAddress((void**)&qk,     g_qk);
    cudaGetSymbolAddress((void**)&phw,    g_phw);
    cudaGetSymbolAddress((void**)&phase,  g_phase);
    cudaGetSymbolAddress((void**)&scores, g_scores);
    cudaGetSymbolAddress((void**)&ssum,   g_ssum);
    cudaGetSymbolAddress((void**)&pcv,    g_pc);
    cudaGetSymbolAddress((void**)&blend,  g_blend);
    cudaGetSymbolAddress((void**)&rowsum, g_rowsum);
    cudaGetSymbolAddress((void**)&xmid,   g_xmid);
    cudaGetSymbolAddress((void**)&x2,     g_x2);
    cudaGetSymbolAddress((void**)&hbuf,   g_hbuf);

    // 1) xn = LN1(x); zero per-head sums; pad phase_w
    ln_kernel<<<NROW, 256>>>(x, ln1_w, ln1_b, xn);
    zero_kernel<<<(BB*NH*SEQ + 255)/256, 256>>>(ssum, BB*NH*SEQ);
    pad_phw_kernel<<<(PDPAD*DIM + 255)/256, 256>>>(phase_w, phw);

    // 2) qk = xn @ W[0:1536]^T + b           [4096, 1536]
    tgemm<true, 1><<<dim3(NROW/128, 1536/128, 1), 256>>>(
        xn, in_w, qk, NROW, 2*DIM, DIM, DIM, DIM, 2*DIM,
        1, 0,0, 0,0, 0,0, 1.0f, in_b, nullptr, 0, nullptr, 0, nullptr, nullptr);

    // 3) phase = tanh(xn @ phw^T)            [4096, 128] (cols 64..127 = 0)
    tgemm<true, 2><<<dim3(NROW/128, 1, 1), 256>>>(
        xn, phw, phase, NROW, PDPAD, DIM, DIM, DIM, PDPAD,
        1, 0,0, 0,0, 0,0, 1.0f, nullptr, nullptr, 0, nullptr, 0, nullptr, nullptr);

    // 4) scores e = exp(0.125 * q@k^T) + atomic row sums    24 x [2048,2048]
    tgemm<true, 6><<<dim3(SEQ/128, SEQ/128, BB*NH), 256>>>(
        qk, qk + DIM, scores, SEQ, SEQ, DHD, 2*DIM, 2*DIM, SEQ,
        NH, (long)SEQ*2*DIM, (long)DHD, (long)SEQ*2*DIM, (long)DHD,
            (long)NH*SEQ*SEQ, (long)SEQ*SEQ,
        0.125f, nullptr, nullptr, 0, nullptr, 0, nullptr, ssum);

    // 5) pcexp = exp(0.5*alpha*(phase@phase^T) + 0.5*alpha)  2 x [2048,2048]
    tgemm<true, 7><<<dim3(SEQ/128, SEQ/128, BB), 256>>>(
        phase, phase, pcv, SEQ, SEQ, PDIM, PDPAD, PDPAD, SEQ,
        1, (long)SEQ*PDPAD, 0, (long)SEQ*PDPAD, 0, (long)SEQ*SEQ, 0,
        1.0f, nullptr, nullptr, 0, nullptr, 0, alpha, nullptr);

    // 6) blend weights + row sums
    blend_kernel<<<BB*SEQ, 256>>>(scores, ssum, pcv, blend, rowsum);

    // 7) xmid = x + (blend/rowsum) @ xn       2 x [2048, 768]
    tgemm<false, 5><<<dim3(SEQ/128, DIM/128, BB), 256>>>(
        blend, xn, xmid, SEQ, DIM, SEQ, SEQ, DIM, DIM,
        1, (long)SEQ*SEQ, 0, (long)SEQ*DIM, 0, (long)SEQ*DIM, 0,
        1.0f, nullptr, x, (long)SEQ*DIM, rowsum, (long)SEQ, nullptr, nullptr);

    // 8) x2 = LN2(xmid)
    ln_kernel<<<NROW, 256>>>(xmid, ln2_w, ln2_b, x2);

    // 9) h = gelu(x2 @ ff_w1^T + b1)          [4096, 3072]
    tgemm<true, 3><<<dim3(NROW/128, FFD/128, 1), 256>>>(
        x2, ff_w1, hbuf, NROW, FFD, DIM, DIM, DIM, FFD,
        1, 0,0, 0,0, 0,0, 1.0f, ff_b1, nullptr, 0, nullptr, 0, nullptr, nullptr);

    // 10) out = xmid + h @ ff_w2^T + b2       [4096, 768]
    tgemm<true, 4><<<dim3(NROW/128, DIM/128, 1), 256>>>(
        hbuf, ff_w2, out, NROW, DIM, FFD, FFD, FFD, DIM,
        1, 0,0, 0,0, 0,0, 1.0f, ff_b2, xmid, 0, nullptr, 0, nullptr, nullptr);

    (void)in_sizes; (void)n_in; (void)out_size;
}

// round 5
// speedup vs baseline: 2.4177x; 1.0487x over previous
#include <cuda_runtime.h>
#include <math.h>

// Problem dims (fixed by the reference)
#define BB   2
#define SEQ  2048
#define DIM  768
#define NH   12
#define DHD  64
#define FFD  3072
#define PDIM 64
#define PDPAD 128
#define NROW (BB*SEQ)      // 4096

// ---------------- scratch (device globals; no cudaMalloc allowed) ----------
__device__ __align__(16) float g_xn[NROW*DIM];
__device__ __align__(16) float g_qk[NROW*2*DIM];
__device__ __align__(16) float g_phw[PDPAD*DIM];                  // padded phase_w
__device__ __align__(16) float g_phase[NROW*PDPAD];               // padded phase
__device__ __align__(16) float g_scores[(size_t)BB*NH*SEQ*SEQ];   // exp(s/8)
__device__              float g_ssum[BB*NH*SEQ];
__device__ __align__(16) float g_pc[(size_t)BB*SEQ*SEQ];          // exp(a*(pc+1)/2)
__device__ __align__(16) float g_blend[(size_t)BB*SEQ*SEQ];
__device__              float g_rowsum[BB*SEQ];
__device__ __align__(16) float g_xmid[NROW*DIM];
__device__ __align__(16) float g_x2[NROW*DIM];
__device__ __align__(16) float g_hbuf[NROW*FFD];

// ---------------- helpers ----------------------------------------------------
__device__ __forceinline__ float warpReduceSum(float v) {
#pragma unroll
    for (int o = 16; o > 0; o >>= 1) v += __shfl_xor_sync(0xffffffffu, v, o);
    return v;
}
__device__ __forceinline__ float blockReduceSum256(float v, float* sm) {
    v = warpReduceSum(v);
    if ((threadIdx.x & 31) == 0) sm[threadIdx.x >> 5] = v;
    __syncthreads();
    if (threadIdx.x < 32) {
        float t = (threadIdx.x < 8) ? sm[threadIdx.x] : 0.0f;
        t = warpReduceSum(t);
        if (threadIdx.x == 0) sm[0] = t;
    }
    __syncthreads();
    float r = sm[0];
    __syncthreads();
    return r;
}

// Fast exp on the FMA pipe. Max rel err ~3e-6.
__device__ __forceinline__ float fast_exp(float x) {
    x = fmaxf(x, -87.0f);
    float y  = x * 1.4426950408889634f;
    float z  = y + 12582912.0f;
    float nf = z - 12582912.0f;
    float f  = y - nf;
    float p  = 1.3333558146e-3f;
    p = fmaf(p, f, 9.6181291076e-3f);
    p = fmaf(p, f, 5.5504108665e-2f);
    p = fmaf(p, f, 2.4022650696e-1f);
    p = fmaf(p, f, 6.9314718056e-1f);
    p = fmaf(p, f, 1.0f);
    unsigned sb = ((unsigned)__float_as_int(z) + (unsigned)(127 - 0x4B400000)) << 23;
    return p * __int_as_float(sb);
}

__device__ __forceinline__ unsigned cvt_tf32(float x) {
    unsigned r;
    asm("cvt.rna.tf32.f32 %0, %1;" : "=r"(r) : "f"(x));
    return r;
}
__device__ __forceinline__ void mma_tf32(float* c, const unsigned* a, const unsigned* b) {
    asm("mma.sync.aligned.m16n8k8.row.col.f32.tf32.tf32.f32 "
        "{%0,%1,%2,%3}, {%4,%5,%6,%7}, {%8,%9}, {%0,%1,%2,%3};"
        : "+f"(c[0]), "+f"(c[1]), "+f"(c[2]), "+f"(c[3])
        : "r"(a[0]), "r"(a[1]), "r"(a[2]), "r"(a[3]), "r"(b[0]), "r"(b[1]));
}
__device__ __forceinline__ void ldsm_x4(unsigned& r0, unsigned& r1,
                                        unsigned& r2, unsigned& r3, unsigned addr) {
    asm volatile("ldmatrix.sync.aligned.m8n8.x4.shared.b16 {%0,%1,%2,%3}, [%4];"
        : "=r"(r0), "=r"(r1), "=r"(r2), "=r"(r3) : "r"(addr));
}
__device__ __forceinline__ unsigned smem_u32(const void* p) {
    unsigned a;
    asm("{ .reg .u64 t; cvta.to.shared.u64 t, %1; cvt.u32.u64 %0, t; }"
        : "=r"(a) : "l"(p));
    return a;
}

// ---------------- LayerNorm ------------------------------------------------
__global__ void __launch_bounds__(256) ln_kernel(
    const float* __restrict__ x, const float* __restrict__ w,
    const float* __restrict__ b, float* __restrict__ o)
{
    __shared__ float sm[8];
    const float* xr = x + (size_t)blockIdx.x * DIM;
    int t = threadIdx.x;
    float v0 = xr[t], v1 = xr[t + 256], v2 = xr[t + 512];
    float mean = blockReduceSum256(v0 + v1 + v2, sm) * (1.0f / DIM);
    float d0 = v0 - mean, d1 = v1 - mean, d2 = v2 - mean;
    float var = blockReduceSum256(d0*d0 + d1*d1 + d2*d2, sm) * (1.0f / DIM);
    float r = rsqrtf(var + 1e-5f);
    float* orow = o + (size_t)blockIdx.x * DIM;
    orow[t      ] = d0 * r * w[t      ] + b[t      ];
    orow[t + 256] = d1 * r * w[t + 256] + b[t + 256];
    orow[t + 512] = d2 * r * w[t + 512] + b[t + 512];
}

__global__ void __launch_bounds__(256) zero_kernel(float* __restrict__ p, int n) {
    int i = blockIdx.x * 256 + threadIdx.x;
    if (i < n) p[i] = 0.0f;
}

// pad phase_w [64,768] -> [128,768] with zeros
__global__ void __launch_bounds__(256) pad_phw_kernel(
    const float* __restrict__ w, float* __restrict__ o)
{
    int i = blockIdx.x * 256 + threadIdx.x;
    if (i < PDPAD * DIM) o[i] = (i < PDIM * DIM) ? w[i] : 0.0f;
}

// ============================================================================
// tf32 tensor-core GEMM: 128x128x16 CTA tile, 8 warps (2x4), warp 64x32,
// mma.sync m16n8k8, double-buffered smem, ldmatrix.x4 fragment loads.
// TRB=true : B row-major [N,K] -> C = A@B^T ; TRB=false: B [K,N] -> C = A@B.
// EPI: 1=+bias, 2=tanh, 3=bias+exact GELU, 4=bias+residual,
//      5=row-divide(rowsum)+residual, 6=exp(scale*v)+atomic rowsum,
//      7=exp(a2*v + a2), a2 = 0.5*alpha
// ============================================================================
template<bool TRB, int EPI>
__global__ void __launch_bounds__(256) tgemm(
    const float* __restrict__ A, const float* __restrict__ Bm,
    float* __restrict__ C,
    int M, int N, int K, int lda, int ldb, int ldc,
    int zdiv,
    long as1, long as2, long bs1, long bs2, long cs1, long cs2,
    float scale,
    const float* __restrict__ bias,
    const float* __restrict__ res, long ress1,
    const float* __restrict__ rsum, long rsums1,
    const float* __restrict__ alphap,
    float* __restrict__ ssum)
{
    const int BK = 16;
    const int LDR = 20;                 // padded row length in words
    int z = blockIdx.z;
    int z1 = z / zdiv, z2 = z - z1 * zdiv;
    A  += z1 * as1 + z2 * as2;
    Bm += z1 * bs1 + z2 * bs2;
    C  += z1 * cs1 + z2 * cs2;
    if (EPI == 4 || EPI == 5) res  += z1 * ress1;
    if (EPI == 5)             rsum += z1 * rsums1;
    if (EPI == 6)             ssum += (size_t)z * M;

    __shared__ unsigned As[2][128][LDR];
    __shared__ unsigned Bs[2][128][LDR];

    int tid  = threadIdx.x;
    int lane = tid & 31;
    int wid  = tid >> 5;
    int wm   = (wid & 1) * 64;
    int wn   = (wid >> 1) * 32;
    int g    = lane >> 2;
    int tg   = lane & 3;
    int bm = blockIdx.x * 128, bn = blockIdx.y * 128;

    float acc[4][4][4];
#pragma unroll
    for (int i = 0; i < 4; i++)
#pragma unroll
        for (int j = 0; j < 4; j++)
#pragma unroll
            for (int r = 0; r < 4; r++) acc[i][j][r] = 0.0f;

    const float* Ab = A + (size_t)bm * lda;

    // staging coords
    int ra = tid >> 2, fa = (tid & 3) << 2;
    int kr = tid >> 5, nc = (tid & 31) << 2;

    // ldmatrix per-lane addresses (buffer 0, ks 0)
    const unsigned BUFSTRIDE = 128 * LDR * 4;
    int mi = lane >> 3, lr = lane & 7;
    unsigned aAddr[4], bAddr[2];
    {
        unsigned asb = smem_u32(&As[0][0][0]);
        unsigned bsb = smem_u32(&Bs[0][0][0]);
#pragma unroll
        for (int mt = 0; mt < 4; mt++)
            aAddr[mt] = asb + (((wm + mt * 16 + (mi & 1) * 8 + lr) * LDR) + (mi >> 1) * 4) * 4;
#pragma unroll
        for (int p = 0; p < 2; p++)
            bAddr[p] = bsb + (((wn + (p * 2 + (mi >> 1)) * 8 + lr) * LDR) + (mi & 1) * 4) * 4;
    }

    float4 sA0, sA1, sB0, sB1;
    // ---- load tile k0=0 ----
    sA0 = *(const float4*)(Ab + (size_t)ra * lda + fa);
    sA1 = *(const float4*)(Ab + (size_t)(ra + 64) * lda + fa);
    if (TRB) {
        sB0 = *(const float4*)(Bm + (size_t)(bn + ra) * ldb + fa);
        sB1 = *(const float4*)(Bm + (size_t)(bn + ra + 64) * ldb + fa);
    } else {
        sB0 = *(const float4*)(Bm + (size_t)kr * ldb + (bn + nc));
        sB1 = *(const float4*)(Bm + (size_t)(kr + 8) * ldb + (bn + nc));
    }

    auto commit = [&](int buf, const float4& a0, const float4& a1,
                      const float4& b0, const float4& b1) {
        uint4 ca0 = {cvt_tf32(a0.x), cvt_tf32(a0.y), cvt_tf32(a0.z), cvt_tf32(a0.w)};
        uint4 ca1 = {cvt_tf32(a1.x), cvt_tf32(a1.y), cvt_tf32(a1.z), cvt_tf32(a1.w)};
        *(uint4*)&As[buf][ra][fa]      = ca0;
        *(uint4*)&As[buf][ra + 64][fa] = ca1;
        if (TRB) {
            uint4 cb0 = {cvt_tf32(b0.x), cvt_tf32(b0.y), cvt_tf32(b0.z), cvt_tf32(b0.w)};
            uint4 cb1 = {cvt_tf32(b1.x), cvt_tf32(b1.y), cvt_tf32(b1.z), cvt_tf32(b1.w)};
            *(uint4*)&Bs[buf][ra][fa]      = cb0;
            *(uint4*)&Bs[buf][ra + 64][fa] = cb1;
        } else {
            Bs[buf][nc + 0][kr] = cvt_tf32(b0.x);
            Bs[buf][nc + 1][kr] = cvt_tf32(b0.y);
            Bs[buf][nc + 2][kr] = cvt_tf32(b0.z);
            Bs[buf][nc + 3][kr] = cvt_tf32(b0.w);
            Bs[buf][nc + 0][kr + 8] = cvt_tf32(b1.x);
            Bs[buf][nc + 1][kr + 8] = cvt_tf32(b1.y);
            Bs[buf][nc + 2][kr + 8] = cvt_tf32(b1.z);
            Bs[buf][nc + 3][kr + 8] = cvt_tf32(b1.w);
        }
    };

    commit(0, sA0, sA1, sB0, sB1);
    __syncthreads();

    int buf = 0;
    for (int k0 = 0; k0 < K; k0 += BK) {
        int kn = k0 + BK;
        if (kn < K) {
            sA0 = *(const float4*)(Ab + (size_t)ra * lda + (kn + fa));
            sA1 = *(const float4*)(Ab + (size_t)(ra + 64) * lda + (kn + fa));
            if (TRB) {
                sB0 = *(const float4*)(Bm + (size_t)(bn + ra) * ldb + (kn + fa));
                sB1 = *(const float4*)(Bm + (size_t)(bn + ra + 64) * ldb + (kn + fa));
            } else {
                sB0 = *(const float4*)(Bm + (size_t)(kn + kr) * ldb + (bn + nc));
                sB1 = *(const float4*)(Bm + (size_t)(kn + kr + 8) * ldb + (bn + nc));
            }
        }

        unsigned bofs = buf * BUFSTRIDE;
#pragma unroll
        for (int ks = 0; ks < 2; ks++) {
            unsigned kofs = bofs + ks * 32;     // 8 words = 32 bytes
            unsigned afr[4][4], bfr[4][2];
#pragma unroll
            for (int mt = 0; mt < 4; mt++)
                ldsm_x4(afr[mt][0], afr[mt][1], afr[mt][2], afr[mt][3],
                        aAddr[mt] + kofs);
            ldsm_x4(bfr[0][0], bfr[0][1], bfr[1][0], bfr[1][1], bAddr[0] + kofs);
            ldsm_x4(bfr[2][0], bfr[2][1], bfr[3][0], bfr[3][1], bAddr[1] + kofs);
#pragma unroll
            for (int mt = 0; mt < 4; mt++)
#pragma unroll
                for (int nt = 0; nt < 4; nt++)
                    mma_tf32(acc[mt][nt], afr[mt], bfr[nt]);
        }

        if (kn < K) {
            int nb = buf ^ 1;
            commit(nb, sA0, sA1, sB0, sB1);
            __syncthreads();
            buf = nb;
        }
    }

    // ---------------- epilogue ----------------
    float a2v = 0.0f;
    if (EPI == 7) a2v = 0.5f * (*alphap);

#pragma unroll
    for (int mt = 0; mt < 4; mt++) {
#pragma unroll
        for (int half = 0; half < 2; half++) {
            int m = bm + wm + mt * 16 + g + half * 8;
            float rinv = 0.0f;
            if (EPI == 5) rinv = 1.0f / rsum[m];
            float rs = 0.0f;
#pragma unroll
            for (int nt = 0; nt < 4; nt++) {
                int c = bn + wn + nt * 8 + tg * 2;
                float v0 = acc[mt][nt][half * 2];
                float v1 = acc[mt][nt][half * 2 + 1];
                if (EPI == 1) { v0 += bias[c]; v1 += bias[c + 1]; }
                if (EPI == 2) { v0 = tanhf(v0); v1 = tanhf(v1); }
                if (EPI == 3) {
                    v0 += bias[c]; v1 += bias[c + 1];
                    v0 = 0.5f * v0 * (1.0f + erff(v0 * 0.70710678118654752f));
                    v1 = 0.5f * v1 * (1.0f + erff(v1 * 0.70710678118654752f));
                }
                if (EPI == 4) {
                    const float2 rr = *(const float2*)(res + (size_t)m * ldc + c);
                    v0 += bias[c] + rr.x; v1 += bias[c + 1] + rr.y;
                }
                if (EPI == 5) {
                    const float2 rr = *(const float2*)(res + (size_t)m * ldc + c);
                    v0 = v0 * rinv + rr.x; v1 = v1 * rinv + rr.y;
                }
                if (EPI == 6) { v0 = fast_exp(v0 * scale); v1 = fast_exp(v1 * scale); }
                if (EPI == 7) { v0 = fast_exp(fmaf(v0, a2v, a2v)); v1 = fast_exp(fmaf(v1, a2v, a2v)); }
                if (EPI == 6) rs += v0 + v1;
                float2 o; o.x = v0; o.y = v1;
                *(float2*)(C + (size_t)m * ldc + c) = o;
            }
            if (EPI == 6) {
                rs += __shfl_xor_sync(0xffffffffu, rs, 1);
                rs += __shfl_xor_sync(0xffffffffu, rs, 2);
                if (tg == 0) atomicAdd(&ssum[m], rs);
            }
        }
    }
}

// --------- blend: u = (mean_h softmax_h + 1e-6) * pcexp; rowsum -------------
__global__ void __launch_bounds__(256) blend_kernel(
    const float* __restrict__ scoresE, const float* __restrict__ ssum,
    const float* __restrict__ pcexp, float* __restrict__ blend,
    float* __restrict__ rowsum)
{
    __shared__ float sm[8];
    __shared__ float sinvl[NH];
    int b = blockIdx.x / SEQ;
    int i = blockIdx.x - b * SEQ;
    if (threadIdx.x < NH)
        sinvl[threadIdx.x] = 1.0f / (ssum[(b * NH + threadIdx.x) * SEQ + i] * (float)NH);
    __syncthreads();

    const float* ebase = scoresE + ((size_t)(b * NH) * SEQ + (size_t)i) * SEQ;
    const float* prow  = pcexp + ((size_t)b * SEQ + i) * SEQ;
    float*       brow  = blend + ((size_t)b * SEQ + i) * SEQ;

    float lsum = 0.0f;
    for (int j = threadIdx.x; j < SEQ; j += 256) {
        float w = 1e-6f;
#pragma unroll
        for (int h = 0; h < NH; h++)
            w = fmaf(ebase[(size_t)h * SEQ * SEQ + j], sinvl[h], w);
        float u = w * prow[j];
        brow[j] = u;
        lsum += u;
    }
    lsum = blockReduceSum256(lsum, sm);
    if (threadIdx.x == 0) rowsum[blockIdx.x] = lsum;
}

// ---------------------------------------------------------------------------
extern "C" void kernel_launch(void* const* d_in, const int* in_sizes, int n_in,
                              void* d_out, int out_size)
{
    const float* x        = (const float*)d_in[0];
    const float* ln1_w    = (const float*)d_in[1];
    const float* ln1_b    = (const float*)d_in[2];
    const float* in_w     = (const float*)d_in[3];
    const float* in_b     = (const float*)d_in[4];
    const float* phase_w  = (const float*)d_in[5];
    const float* alpha    = (const float*)d_in[6];
    const float* ff_w1    = (const float*)d_in[7];
    const float* ff_b1    = (const float*)d_in[8];
    const float* ff_w2    = (const float*)d_in[9];
    const float* ff_b2    = (const float*)d_in[10];
    const float* ln2_w    = (const float*)d_in[11];
    const float* ln2_b    = (const float*)d_in[12];
    float* out            = (float*)d_out;

    float *xn, *qk, *phw, *phase, *scores, *ssum, *pcv, *blend, *rowsum, *xmid, *x2, *hbuf;
    cudaGetSymbolAddress((void**)&xn,     g_xn);
    cudaGetSymbolAddress((void**)&qk,     g_qk);
    cudaGetSymbolAddress((void**)&phw,    g_phw);
    cudaGetSymbolAddress((void**)&phase,  g_phase);
    cudaGetSymbolAddress((void**)&scores, g_scores);
    cudaGetSymbolAddress((void**)&ssum,   g_ssum);
    cudaGetSymbolAddress((void**)&pcv,    g_pc);
    cudaGetSymbolAddress((void**)&blend,  g_blend);
    cudaGetSymbolAddress((void**)&rowsum, g_rowsum);
    cudaGetSymbolAddress((void**)&xmid,   g_xmid);
    cudaGetSymbolAddress((void**)&x2,     g_x2);
    cudaGetSymbolAddress((void**)&hbuf,   g_hbuf);

    // 1) xn = LN1(x); zero per-head sums; pad phase_w
    ln_kernel<<<NROW, 256>>>(x, ln1_w, ln1_b, xn);
    zero_kernel<<<(BB*NH*SEQ + 255)/256, 256>>>(ssum, BB*NH*SEQ);
    pad_phw_kernel<<<(PDPAD*DIM + 255)/256, 256>>>(phase_w, phw);

    // 2) qk = xn @ W[0:1536]^T + b           [4096, 1536]
    tgemm<true, 1><<<dim3(NROW/128, 1536/128, 1), 256>>>(
        xn, in_w, qk, NROW, 2*DIM, DIM, DIM, DIM, 2*DIM,
        1, 0,0, 0,0, 0,0, 1.0f, in_b, nullptr, 0, nullptr, 0, nullptr, nullptr);

    // 3) phase = tanh(xn @ phw^T)            [4096, 128] (cols 64..127 = 0)
    tgemm<true, 2><<<dim3(NROW/128, 1, 1), 256>>>(
        xn, phw, phase, NROW, PDPAD, DIM, DIM, DIM, PDPAD,
        1, 0,0, 0,0, 0,0, 1.0f, nullptr, nullptr, 0, nullptr, 0, nullptr, nullptr);

    // 4) scores e = exp(0.125 * q@k^T) + atomic row sums    24 x [2048,2048]
    tgemm<true, 6><<<dim3(SEQ/128, SEQ/128, BB*NH), 256>>>(
        qk, qk + DIM, scores, SEQ, SEQ, DHD, 2*DIM, 2*DIM, SEQ,
        NH, (long)SEQ*2*DIM, (long)DHD, (long)SEQ*2*DIM, (long)DHD,
            (long)NH*SEQ*SEQ, (long)SEQ*SEQ,
        0.125f, nullptr, nullptr, 0, nullptr, 0, nullptr, ssum);

    // 5) pcexp = exp(0.5*alpha*(phase@phase^T) + 0.5*alpha)  2 x [2048,2048]
    tgemm<true, 7><<<dim3(SEQ/128, SEQ/128, BB), 256>>>(
        phase, phase, pcv, SEQ, SEQ, PDIM, PDPAD, PDPAD, SEQ,
        1, (long)SEQ*PDPAD, 0, (long)SEQ*PDPAD, 0, (long)SEQ*SEQ, 0,
        1.0f, nullptr, nullptr, 0, nullptr, 0, alpha, nullptr);

    // 6) blend weights + row sums
    blend_kernel<<<BB*SEQ, 256>>>(scores, ssum, pcv, blend, rowsum);

    // 7) xmid = x + (blend/rowsum) @ xn       2 x [2048, 768]
    tgemm<false, 5><<<dim3(SEQ/128, DIM/128, BB), 256>>>(
        blend, xn, xmid, SEQ, DIM, SEQ, SEQ, DIM, DIM,
        1, (long)SEQ*SEQ, 0, (long)SEQ*DIM, 0, (long)SEQ*DIM, 0,
        1.0f, nullptr, x, (long)SEQ*DIM, rowsum, (long)SEQ, nullptr, nullptr);

    // 8) x2 = LN2(xmid)
    ln_kernel<<<NROW, 256>>>(xmid, ln2_w, ln2_b, x2);

    // 9) h = gelu(x2 @ ff_w1^T + b1)          [4096, 3072]
    tgemm<true, 3><<<dim3(NROW/128, FFD/128, 1), 256>>>(
        x2, ff_w1, hbuf, NROW, FFD, DIM, DIM, DIM, FFD,
        1, 0,0, 0,0, 0,0, 1.0f, ff_b1, nullptr, 0, nullptr, 0, nullptr, nullptr);

    // 10) out = xmid + h @ ff_w2^T + b2       [4096, 768]
    tgemm<true, 4><<<dim3(NROW/128, DIM/128, 1), 256>>>(
        hbuf, ff_w2, out, NROW, DIM, FFD, FFD, FFD, DIM,
        1, 0,0, 0,0, 0,0, 1.0f, ff_b2, xmid, 0, nullptr, 0, nullptr, nullptr);

    (void)in_sizes; (void)n_in; (void)out_size;
}

// round 6
// speedup vs baseline: 2.5918x; 1.0720x over previous
#include <cuda_runtime.h>
#include <math.h>

// Problem dims (fixed by the reference)
#define BB   2
#define SEQ  2048
#define DIM  768
#define NH   12
#define DHD  64
#define FFD  3072
#define PDIM 64
#define PDPAD 128
#define NROW (BB*SEQ)      // 4096

#define STAGES 3
#define LDRW   20          // padded row length in 4-byte words
#define SMEM_DYN (STAGES*128*LDRW*4*2)

// ---------------- scratch (device globals; no cudaMalloc allowed) ----------
__device__ __align__(16) float g_xn[NROW*DIM];
__device__ __align__(16) float g_xnT[NROW*DIM];                   // [B][D][S]
__device__ __align__(16) float g_qk[NROW*2*DIM];
__device__ __align__(16) float g_phw[PDPAD*DIM];
__device__ __align__(16) float g_phase[NROW*PDPAD];
__device__ __align__(16) float g_scores[(size_t)BB*NH*SEQ*SEQ];
__device__              float g_ssum[BB*NH*SEQ];
__device__ __align__(16) float g_pc[(size_t)BB*SEQ*SEQ];
__device__ __align__(16) float g_blend[(size_t)BB*SEQ*SEQ];
__device__              float g_rowsum[BB*SEQ];
__device__ __align__(16) float g_xmid[NROW*DIM];
__device__ __align__(16) float g_x2[NROW*DIM];
__device__ __align__(16) float g_hbuf[NROW*FFD];

// ---------------- helpers ----------------------------------------------------
__device__ __forceinline__ float warpReduceSum(float v) {
#pragma unroll
    for (int o = 16; o > 0; o >>= 1) v += __shfl_xor_sync(0xffffffffu, v, o);
    return v;
}
__device__ __forceinline__ float blockReduceSum256(float v, float* sm) {
    v = warpReduceSum(v);
    if ((threadIdx.x & 31) == 0) sm[threadIdx.x >> 5] = v;
    __syncthreads();
    if (threadIdx.x < 32) {
        float t = (threadIdx.x < 8) ? sm[threadIdx.x] : 0.0f;
        t = warpReduceSum(t);
        if (threadIdx.x == 0) sm[0] = t;
    }
    __syncthreads();
    float r = sm[0];
    __syncthreads();
    return r;
}

// Fast exp on the FMA pipe. Max rel err ~3e-6.
__device__ __forceinline__ float fast_exp(float x) {
    x = fmaxf(x, -87.0f);
    float y  = x * 1.4426950408889634f;
    float z  = y + 12582912.0f;
    float nf = z - 12582912.0f;
    float f  = y - nf;
    float p  = 1.3333558146e-3f;
    p = fmaf(p, f, 9.6181291076e-3f);
    p = fmaf(p, f, 5.5504108665e-2f);
    p = fmaf(p, f, 2.4022650696e-1f);
    p = fmaf(p, f, 6.9314718056e-1f);
    p = fmaf(p, f, 1.0f);
    unsigned sb = ((unsigned)__float_as_int(z) + (unsigned)(127 - 0x4B400000)) << 23;
    return p * __int_as_float(sb);
}

__device__ __forceinline__ void mma_tf32(float* c, const unsigned* a, const unsigned* b) {
    asm("mma.sync.aligned.m16n8k8.row.col.f32.tf32.tf32.f32 "
        "{%0,%1,%2,%3}, {%4,%5,%6,%7}, {%8,%9}, {%0,%1,%2,%3};"
        : "+f"(c[0]), "+f"(c[1]), "+f"(c[2]), "+f"(c[3])
        : "r"(a[0]), "r"(a[1]), "r"(a[2]), "r"(a[3]), "r"(b[0]), "r"(b[1]));
}
__device__ __forceinline__ void ldsm_x4(unsigned& r0, unsigned& r1,
                                        unsigned& r2, unsigned& r3, unsigned addr) {
    asm volatile("ldmatrix.sync.aligned.m8n8.x4.shared.b16 {%0,%1,%2,%3}, [%4];"
        : "=r"(r0), "=r"(r1), "=r"(r2), "=r"(r3) : "r"(addr));
}
__device__ __forceinline__ unsigned smem_u32(const void* p) {
    unsigned a;
    asm("{ .reg .u64 t; cvta.to.shared.u64 t, %1; cvt.u32.u64 %0, t; }"
        : "=r"(a) : "l"(p));
    return a;
}
__device__ __forceinline__ void cp_async16(unsigned dst, const void* src) {
    asm volatile("cp.async.cg.shared.global [%0], [%1], 16;" :: "r"(dst), "l"(src));
}

// ---------------- LayerNorm ------------------------------------------------
__global__ void __launch_bounds__(256) ln_kernel(
    const float* __restrict__ x, const float* __restrict__ w,
    const float* __restrict__ b, float* __restrict__ o)
{
    __shared__ float sm[8];
    const float* xr = x + (size_t)blockIdx.x * DIM;
    int t = threadIdx.x;
    float v0 = xr[t], v1 = xr[t + 256], v2 = xr[t + 512];
    float mean = blockReduceSum256(v0 + v1 + v2, sm) * (1.0f / DIM);
    float d0 = v0 - mean, d1 = v1 - mean, d2 = v2 - mean;
    float var = blockReduceSum256(d0*d0 + d1*d1 + d2*d2, sm) * (1.0f / DIM);
    float r = rsqrtf(var + 1e-5f);
    float* orow = o + (size_t)blockIdx.x * DIM;
    orow[t      ] = d0 * r * w[t      ] + b[t      ];
    orow[t + 256] = d1 * r * w[t + 256] + b[t + 256];
    orow[t + 512] = d2 * r * w[t + 512] + b[t + 512];
}

__global__ void __launch_bounds__(256) zero_kernel(float* __restrict__ p, int n) {
    int i = blockIdx.x * 256 + threadIdx.x;
    if (i < n) p[i] = 0.0f;
}

// pad phase_w [64,768] -> [128,768] with zeros
__global__ void __launch_bounds__(256) pad_phw_kernel(
    const float* __restrict__ w, float* __restrict__ o)
{
    int i = blockIdx.x * 256 + threadIdx.x;
    if (i < PDPAD * DIM) o[i] = (i < PDIM * DIM) ? w[i] : 0.0f;
}

// transpose per batch: in [SEQ][DIM] -> out [DIM][SEQ]
__global__ void __launch_bounds__(256) transpose_kernel(
    const float* __restrict__ in, float* __restrict__ out)
{
    __shared__ float t[32][33];
    int b = blockIdx.z;
    const float* ib = in + (size_t)b * SEQ * DIM;
    float* ob = out + (size_t)b * SEQ * DIM;
    int tx = threadIdx.x & 31, ty = threadIdx.x >> 5;
    int sbase = blockIdx.x * 32;   // SEQ tile
    int dbase = blockIdx.y * 32;   // DIM tile
#pragma unroll
    for (int i = 0; i < 32; i += 8)
        t[ty + i][tx] = ib[(size_t)(sbase + ty + i) * DIM + dbase + tx];
    __syncthreads();
#pragma unroll
    for (int i = 0; i < 32; i += 8)
        ob[(size_t)(dbase + ty + i) * SEQ + sbase + tx] = t[tx][ty + i];
}

// ============================================================================
// tf32 tensor-core GEMM: 128x128x16 CTA tile, 8 warps (2x4), warp 64x32,
// mma.sync m16n8k8, 3-stage cp.async pipeline, ldmatrix.x4 fragment loads.
// B is always row-major [N,K]: C = A @ B^T.
// EPI: 1=+bias, 2=tanh, 3=bias+exact GELU, 4=bias+residual,
//      5=row-divide(rowsum)+residual, 6=exp(scale*v)+atomic rowsum,
//      7=exp(a2*v + a2), a2 = 0.5*alpha
// ============================================================================
template<int EPI>
__global__ void __launch_bounds__(256) tgemm(
    const float* __restrict__ A, const float* __restrict__ Bm,
    float* __restrict__ C,
    int M, int N, int K, int lda, int ldb, int ldc,
    int zdiv,
    long as1, long as2, long bs1, long bs2, long cs1, long cs2,
    float scale,
    const float* __restrict__ bias,
    const float* __restrict__ res, long ress1,
    const float* __restrict__ rsum, long rsums1,
    const float* __restrict__ alphap,
    float* __restrict__ ssum)
{
    const int BK = 16;
    extern __shared__ unsigned sh[];
    unsigned* Asb = sh;                               // [STAGES][128][LDRW]
    unsigned* Bsb = sh + STAGES * 128 * LDRW;
    const unsigned STAGE_BYTES = 128 * LDRW * 4;

    int z = blockIdx.z;
    int z1 = z / zdiv, z2 = z - z1 * zdiv;
    A  += z1 * as1 + z2 * as2;
    Bm += z1 * bs1 + z2 * bs2;
    C  += z1 * cs1 + z2 * cs2;
    if (EPI == 4 || EPI == 5) res  += z1 * ress1;
    if (EPI == 5)             rsum += z1 * rsums1;
    if (EPI == 6)             ssum += (size_t)z * M;

    int tid  = threadIdx.x;
    int lane = tid & 31;
    int wid  = tid >> 5;
    int wm   = (wid & 1) * 64;
    int wn   = (wid >> 1) * 32;
    int g    = lane >> 2;
    int tg   = lane & 3;
    int bm = blockIdx.x * 128, bn = blockIdx.y * 128;

    float acc[4][4][4];
#pragma unroll
    for (int i = 0; i < 4; i++)
#pragma unroll
        for (int j = 0; j < 4; j++)
#pragma unroll
            for (int r = 0; r < 4; r++) acc[i][j][r] = 0.0f;

    const float* Ab = A + (size_t)bm * lda;
    const float* Bb = Bm + (size_t)bn * ldb;

    // cp.async staging: thread -> row r0 = tid/2, float col cc = (tid&1)*8, 2x16B each
    int r0 = tid >> 1;
    int cc = (tid & 1) << 3;
    unsigned asBase = smem_u32(Asb);
    unsigned bsBase = smem_u32(Bsb);
    unsigned aDst = asBase + (r0 * LDRW + cc) * 4;
    unsigned bDst = bsBase + (r0 * LDRW + cc) * 4;
    const float* aSrc = Ab + (size_t)r0 * lda + cc;
    const float* bSrc = Bb + (size_t)r0 * ldb + cc;

    // ldmatrix per-lane addresses (stage 0)
    int mi = lane >> 3, lr = lane & 7;
    unsigned aAddr[4], bAddr[2];
#pragma unroll
    for (int mt = 0; mt < 4; mt++)
        aAddr[mt] = asBase + (((wm + mt * 16 + (mi & 1) * 8 + lr) * LDRW) + (mi >> 1) * 4) * 4;
#pragma unroll
    for (int p = 0; p < 2; p++)
        bAddr[p] = bsBase + (((wn + (p * 2 + (mi >> 1)) * 8 + lr) * LDRW) + (mi & 1) * 4) * 4;

    auto stage_load = [&](int st, int k0) {
        if (k0 < K) {
            unsigned so = st * STAGE_BYTES;
            cp_async16(aDst + so,      aSrc + k0);
            cp_async16(aDst + so + 16, aSrc + k0 + 4);
            cp_async16(bDst + so,      bSrc + k0);
            cp_async16(bDst + so + 16, bSrc + k0 + 4);
        }
        asm volatile("cp.async.commit_group;");
    };

    stage_load(0, 0);
    stage_load(1, BK);

    int s = 0;
    for (int k0 = 0; k0 < K; k0 += BK) {
        asm volatile("cp.async.wait_group 1;");
        __syncthreads();
        int s2 = s + 2; if (s2 >= STAGES) s2 -= STAGES;
        stage_load(s2, k0 + 2 * BK);

        unsigned so = s * STAGE_BYTES;
#pragma unroll
        for (int ks = 0; ks < 2; ks++) {
            unsigned kofs = so + ks * 32;
            unsigned afr[4][4], bfr[4][2];
#pragma unroll
            for (int mt = 0; mt < 4; mt++)
                ldsm_x4(afr[mt][0], afr[mt][1], afr[mt][2], afr[mt][3],
                        aAddr[mt] + kofs);
            ldsm_x4(bfr[0][0], bfr[0][1], bfr[1][0], bfr[1][1], bAddr[0] + kofs);
            ldsm_x4(bfr[2][0], bfr[2][1], bfr[3][0], bfr[3][1], bAddr[1] + kofs);
#pragma unroll
            for (int mt = 0; mt < 4; mt++)
#pragma unroll
                for (int nt = 0; nt < 4; nt++)
                    mma_tf32(acc[mt][nt], afr[mt], bfr[nt]);
        }
        if (++s >= STAGES) s = 0;
    }

    // ---------------- epilogue ----------------
    float a2v = 0.0f;
    if (EPI == 7) a2v = 0.5f * (*alphap);

#pragma unroll
    for (int mt = 0; mt < 4; mt++) {
#pragma unroll
        for (int half = 0; half < 2; half++) {
            int m = bm + wm + mt * 16 + g + half * 8;
            float rinv = 0.0f;
            if (EPI == 5) rinv = 1.0f / rsum[m];
            float rs = 0.0f;
#pragma unroll
            for (int nt = 0; nt < 4; nt++) {
                int c = bn + wn + nt * 8 + tg * 2;
                float v0 = acc[mt][nt][half * 2];
                float v1 = acc[mt][nt][half * 2 + 1];
                if (EPI == 1) { v0 += bias[c]; v1 += bias[c + 1]; }
                if (EPI == 2) { v0 = tanhf(v0); v1 = tanhf(v1); }
                if (EPI == 3) {
                    v0 += bias[c]; v1 += bias[c + 1];
                    v0 = 0.5f * v0 * (1.0f + erff(v0 * 0.70710678118654752f));
                    v1 = 0.5f * v1 * (1.0f + erff(v1 * 0.70710678118654752f));
                }
                if (EPI == 4) {
                    const float2 rr = *(const float2*)(res + (size_t)m * ldc + c);
                    v0 += bias[c] + rr.x; v1 += bias[c + 1] + rr.y;
                }
                if (EPI == 5) {
                    const float2 rr = *(const float2*)(res + (size_t)m * ldc + c);
                    v0 = v0 * rinv + rr.x; v1 = v1 * rinv + rr.y;
                }
                if (EPI == 6) { v0 = fast_exp(v0 * scale); v1 = fast_exp(v1 * scale); }
                if (EPI == 7) { v0 = fast_exp(fmaf(v0, a2v, a2v)); v1 = fast_exp(fmaf(v1, a2v, a2v)); }
                if (EPI == 6) rs += v0 + v1;
                float2 o; o.x = v0; o.y = v1;
                *(float2*)(C + (size_t)m * ldc + c) = o;
            }
            if (EPI == 6) {
                rs += __shfl_xor_sync(0xffffffffu, rs, 1);
                rs += __shfl_xor_sync(0xffffffffu, rs, 2);
                if (tg == 0) atomicAdd(&ssum[m], rs);
            }
        }
    }
}

// --------- blend: u = (mean_h softmax_h + 1e-6) * pcexp; rowsum -------------
__global__ void __launch_bounds__(256) blend_kernel(
    const float* __restrict__ scoresE, const float* __restrict__ ssum,
    const float* __restrict__ pcexp, float* __restrict__ blend,
    float* __restrict__ rowsum)
{
    __shared__ float sm[8];
    __shared__ float sinvl[NH];
    int b = blockIdx.x / SEQ;
    int i = blockIdx.x - b * SEQ;
    if (threadIdx.x < NH)
        sinvl[threadIdx.x] = 1.0f / (ssum[(b * NH + threadIdx.x) * SEQ + i] * (float)NH);
    __syncthreads();

    const float* ebase = scoresE + ((size_t)(b * NH) * SEQ + (size_t)i) * SEQ;
    const float* prow  = pcexp + ((size_t)b * SEQ + i) * SEQ;
    float*       brow  = blend + ((size_t)b * SEQ + i) * SEQ;

    float lsum = 0.0f;
    for (int j = threadIdx.x; j < SEQ; j += 256) {
        float w = 1e-6f;
#pragma unroll
        for (int h = 0; h < NH; h++)
            w = fmaf(ebase[(size_t)h * SEQ * SEQ + j], sinvl[h], w);
        float u = w * prow[j];
        brow[j] = u;
        lsum += u;
    }
    lsum = blockReduceSum256(lsum, sm);
    if (threadIdx.x == 0) rowsum[blockIdx.x] = lsum;
}

// ---------------------------------------------------------------------------
extern "C" void kernel_launch(void* const* d_in, const int* in_sizes, int n_in,
                              void* d_out, int out_size)
{
    const float* x        = (const float*)d_in[0];
    const float* ln1_w    = (const float*)d_in[1];
    const float* ln1_b    = (const float*)d_in[2];
    const float* in_w     = (const float*)d_in[3];
    const float* in_b     = (const float*)d_in[4];
    const float* phase_w  = (const float*)d_in[5];
    const float* alpha    = (const float*)d_in[6];
    const float* ff_w1    = (const float*)d_in[7];
    const float* ff_b1    = (const float*)d_in[8];
    const float* ff_w2    = (const float*)d_in[9];
    const float* ff_b2    = (const float*)d_in[10];
    const float* ln2_w    = (const float*)d_in[11];
    const float* ln2_b    = (const float*)d_in[12];
    float* out            = (float*)d_out;

    float *xn, *xnT, *qk, *phw, *phase, *scores, *ssum, *pcv, *blend, *rowsum, *xmid, *x2, *hbuf;
    cudaGetSymbolAddress((void**)&xn,     g_xn);
    cudaGetSymbolAddress((void**)&xnT,    g_xnT);
    cudaGetSymbolAddress((void**)&qk,     g_qk);
    cudaGetSymbolAddress((void**)&phw,    g_phw);
    cudaGetSymbolAddress((void**)&phase,  g_phase);
    cudaGetSymbolAddress((void**)&scores, g_scores);
    cudaGetSymbolAddress((void**)&ssum,   g_ssum);
    cudaGetSymbolAddress((void**)&pcv,    g_pc);
    cudaGetSymbolAddress((void**)&blend,  g_blend);
    cudaGetSymbolAddress((void**)&rowsum, g_rowsum);
    cudaGetSymbolAddress((void**)&xmid,   g_xmid);
    cudaGetSymbolAddress((void**)&x2,     g_x2);
    cudaGetSymbolAddress((void**)&hbuf,   g_hbuf);

    // allow 60KB dynamic smem on all tgemm instantiations
    cudaFuncSetAttribute(tgemm<1>, cudaFuncAttributeMaxDynamicSharedMemorySize, SMEM_DYN);
    cudaFuncSetAttribute(tgemm<2>, cudaFuncAttributeMaxDynamicSharedMemorySize, SMEM_DYN);
    cudaFuncSetAttribute(tgemm<3>, cudaFuncAttributeMaxDynamicSharedMemorySize, SMEM_DYN);
    cudaFuncSetAttribute(tgemm<4>, cudaFuncAttributeMaxDynamicSharedMemorySize, SMEM_DYN);
    cudaFuncSetAttribute(tgemm<5>, cudaFuncAttributeMaxDynamicSharedMemorySize, SMEM_DYN);
    cudaFuncSetAttribute(tgemm<6>, cudaFuncAttributeMaxDynamicSharedMemorySize, SMEM_DYN);
    cudaFuncSetAttribute(tgemm<7>, cudaFuncAttributeMaxDynamicSharedMemorySize, SMEM_DYN);

    // 1) xn = LN1(x); xnT; zero per-head sums; pad phase_w
    ln_kernel<<<NROW, 256>>>(x, ln1_w, ln1_b, xn);
    zero_kernel<<<(BB*NH*SEQ + 255)/256, 256>>>(ssum, BB*NH*SEQ);
    pad_phw_kernel<<<(PDPAD*DIM + 255)/256, 256>>>(phase_w, phw);
    transpose_kernel<<<dim3(SEQ/32, DIM/32, BB), 256>>>(xn, xnT);

    // 2) qk = xn @ W[0:1536]^T + b           [4096, 1536]
    tgemm<1><<<dim3(NROW/128, 1536/128, 1), 256, SMEM_DYN>>>(
        xn, in_w, qk, NROW, 2*DIM, DIM, DIM, DIM, 2*DIM,
        1, 0,0, 0,0, 0,0, 1.0f, in_b, nullptr, 0, nullptr, 0, nullptr, nullptr);

    // 3) phase = tanh(xn @ phw^T)            [4096, 128] (cols 64..127 = 0)
    tgemm<2><<<dim3(NROW/128, 1, 1), 256, SMEM_DYN>>>(
        xn, phw, phase, NROW, PDPAD, DIM, DIM, DIM, PDPAD,
        1, 0,0, 0,0, 0,0, 1.0f, nullptr, nullptr, 0, nullptr, 0, nullptr, nullptr);

    // 4) scores e = exp(0.125 * q@k^T) + atomic row sums    24 x [2048,2048]
    tgemm<6><<<dim3(SEQ/128, SEQ/128, BB*NH), 256, SMEM_DYN>>>(
        qk, qk + DIM, scores, SEQ, SEQ, DHD, 2*DIM, 2*DIM, SEQ,
        NH, (long)SEQ*2*DIM, (long)DHD, (long)SEQ*2*DIM, (long)DHD,
            (long)NH*SEQ*SEQ, (long)SEQ*SEQ,
        0.125f, nullptr, nullptr, 0, nullptr, 0, nullptr, ssum);

    // 5) pcexp = exp(0.5*alpha*(phase@phase^T) + 0.5*alpha)  2 x [2048,2048]
    tgemm<7><<<dim3(SEQ/128, SEQ/128, BB), 256, SMEM_DYN>>>(
        phase, phase, pcv, SEQ, SEQ, PDIM, PDPAD, PDPAD, SEQ,
        1, (long)SEQ*PDPAD, 0, (long)SEQ*PDPAD, 0, (long)SEQ*SEQ, 0,
        1.0f, nullptr, nullptr, 0, nullptr, 0, alpha, nullptr);

    // 6) blend weights + row sums
    blend_kernel<<<BB*SEQ, 256>>>(scores, ssum, pcv, blend, rowsum);

    // 7) xmid = x + (blend/rowsum) @ xnT^T    2 x [2048, 768]
    tgemm<5><<<dim3(SEQ/128, DIM/128, BB), 256, SMEM_DYN>>>(
        blend, xnT, xmid, SEQ, DIM, SEQ, SEQ, SEQ, DIM,
        1, (long)SEQ*SEQ, 0, (long)DIM*SEQ, 0, (long)SEQ*DIM, 0,
        1.0f, nullptr, x, (long)SEQ*DIM, rowsum, (long)SEQ, nullptr, nullptr);

    // 8) x2 = LN2(xmid)
    ln_kernel<<<NROW, 256>>>(xmid, ln2_w, ln2_b, x2);

    // 9) h = gelu(x2 @ ff_w1^T + b1)          [4096, 3072]
    tgemm<3><<<dim3(NROW/128, FFD/128, 1), 256, SMEM_DYN>>>(
        x2, ff_w1, hbuf, NROW, FFD, DIM, DIM, DIM, FFD,
        1, 0,0, 0,0, 0,0, 1.0f, ff_b1, nullptr, 0, nullptr, 0, nullptr, nullptr);

    // 10) out = xmid + h @ ff_w2^T + b2       [4096, 768]
    tgemm<4><<<dim3(NROW/128, DIM/128, 1), 256, SMEM_DYN>>>(
        hbuf, ff_w2, out, NROW, DIM, FFD, FFD, FFD, DIM,
        1, 0,0, 0,0, 0,0, 1.0f, ff_b2, xmid, 0, nullptr, 0, nullptr, nullptr);

    (void)in_sizes; (void)n_in; (void)out_size;
}